// round 3
// baseline (speedup 1.0000x reference)
#include <cuda_runtime.h>
#include <math.h>

#define NTOK   8192
#define DMODEL 512
#define DFF    2048
#define NEXP   8
#define KMAX   4
#define TOPP   0.9f

// ---------------- scratch (static device globals; no allocations) ----------
__device__ float g_H[(size_t)NTOK * DFF];       // 64 MB: gelu(X@W1+b1) per expert
__device__ float g_w[NTOK * NEXP];              // dense combine weights (0 if unselected)
__device__ float g_cnt[NEXP];                   // aux: per-expert assignment counts
__device__ float g_psum[NEXP];                  // aux: per-expert prob sums

// ---------------- init ------------------------------------------------------
__global__ void init_kernel() {
    int i = threadIdx.x;
    if (i < NEXP) { g_cnt[i] = 0.f; g_psum[i] = 0.f; }
}

// ---------------- router: logits + softmax + top-p + aux accum --------------
// 1 warp per token, 8 warps per block.
__global__ void router_kernel(const float* __restrict__ x,
                              const float* __restrict__ rw) {
    __shared__ float s_rw[DMODEL * NEXP];
    __shared__ float s_cnt[NEXP];
    __shared__ float s_psum[NEXP];
    int tid = threadIdx.x;
    if (tid < NEXP) { s_cnt[tid] = 0.f; s_psum[tid] = 0.f; }
    for (int i = tid; i < DMODEL * NEXP / 4; i += blockDim.x)
        ((float4*)s_rw)[i] = ((const float4*)rw)[i];
    __syncthreads();

    int warp = tid >> 5, lane = tid & 31;
    int t = blockIdx.x * 8 + warp;

    float acc[NEXP];
#pragma unroll
    for (int e = 0; e < NEXP; e++) acc[e] = 0.f;
    const float* xr = x + (size_t)t * DMODEL;
    for (int k = lane; k < DMODEL; k += 32) {
        float xv = xr[k];
        float4 r0 = *(const float4*)&s_rw[k * 8];
        float4 r1 = *(const float4*)&s_rw[k * 8 + 4];
        acc[0] = fmaf(xv, r0.x, acc[0]); acc[1] = fmaf(xv, r0.y, acc[1]);
        acc[2] = fmaf(xv, r0.z, acc[2]); acc[3] = fmaf(xv, r0.w, acc[3]);
        acc[4] = fmaf(xv, r1.x, acc[4]); acc[5] = fmaf(xv, r1.y, acc[5]);
        acc[6] = fmaf(xv, r1.z, acc[6]); acc[7] = fmaf(xv, r1.w, acc[7]);
    }
#pragma unroll
    for (int e = 0; e < NEXP; e++) {
#pragma unroll
        for (int o = 16; o > 0; o >>= 1)
            acc[e] += __shfl_xor_sync(0xffffffffu, acc[e], o);
    }

    if (lane == 0) {
        float mx = acc[0];
#pragma unroll
        for (int e = 1; e < NEXP; e++) mx = fmaxf(mx, acc[e]);
        float p[NEXP]; float s = 0.f;
#pragma unroll
        for (int e = 0; e < NEXP; e++) { p[e] = expf(acc[e] - mx); s += p[e]; }
        float inv = 1.f / s;
#pragma unroll
        for (int e = 0; e < NEXP; e++) p[e] *= inv;
#pragma unroll
        for (int e = 0; e < NEXP; e++) atomicAdd(&s_psum[e], p[e]);

        // top-4 by selection (ties -> lowest index, matches lax.top_k)
        float tmp[NEXP];
#pragma unroll
        for (int e = 0; e < NEXP; e++) tmp[e] = p[e];
        float sp[KMAX]; int si[KMAX];
        for (int j = 0; j < KMAX; j++) {
            float best = tmp[0]; int bi = 0;
            for (int e = 1; e < NEXP; e++)
                if (tmp[e] > best) { best = tmp[e]; bi = e; }
            sp[j] = best; si[j] = bi; tmp[bi] = -1.f;
        }
        // top-p keep: shifted-cumsum < 0.9 OR slot < MIN_EXPERTS(=1)
        float csum = 0.f, wsum = 0.f; bool keep[KMAX];
        for (int j = 0; j < KMAX; j++) {
            keep[j] = (j < 1) || (csum < TOPP);
            csum += sp[j];
            if (keep[j]) wsum += sp[j];
        }
        wsum = fmaxf(wsum, 1e-9f);
        float wout[NEXP];
#pragma unroll
        for (int e = 0; e < NEXP; e++) wout[e] = 0.f;
        for (int j = 0; j < KMAX; j++)
            if (keep[j]) { wout[si[j]] = sp[j] / wsum; atomicAdd(&s_cnt[si[j]], 1.f); }
#pragma unroll
        for (int e = 0; e < NEXP; e++) g_w[t * NEXP + e] = wout[e];
    }
    __syncthreads();
    if (tid < NEXP) {
        atomicAdd(&g_cnt[tid], s_cnt[tid]);
        atomicAdd(&g_psum[tid], s_psum[tid]);
    }
}

// ---------------- aux finalize ----------------------------------------------
__global__ void aux_kernel(float* __restrict__ out_aux) {
    if (threadIdx.x == 0) {
        float tot = 0.f;
        for (int e = 0; e < NEXP; e++) tot += g_cnt[e];
        tot = fmaxf(tot, 1.f);
        float a = 0.f;
        for (int e = 0; e < NEXP; e++)
            a += (g_cnt[e] / tot) * (g_psum[e] / (float)NTOK);
        *out_aux = 0.01f * (float)NEXP * a;
    }
}

// ---------------- SGEMM core: 128x128 tile, 8x8 regs, 256 threads ----------
#define BM 128
#define BN 128
#define BK 16
#define TM 8
#define TN 8

__device__ __forceinline__ void sgemm_core(
    const float* __restrict__ A, int lda,     // already offset to (m0, 0)
    const float* __restrict__ B, int ldb,     // already offset to (0, n0)
    int K, float acc[TM][TN], float* As, float* Bs) {
    int tid = threadIdx.x;
#pragma unroll
    for (int i = 0; i < TM; i++)
#pragma unroll
        for (int j = 0; j < TN; j++) acc[i][j] = 0.f;

    int tx = tid & 15, ty = tid >> 4;

    for (int k0 = 0; k0 < K; k0 += BK) {
        // A tile: 128x16 -> As[k][m] (transposed store)
#pragma unroll
        for (int s = 0; s < 2; s++) {
            int slot = tid * 2 + s;           // 0..511
            int row = slot >> 2;
            int cg = slot & 3;
            float4 v = *(const float4*)(A + (size_t)row * lda + k0 + cg * 4);
            As[(cg * 4 + 0) * BM + row] = v.x;
            As[(cg * 4 + 1) * BM + row] = v.y;
            As[(cg * 4 + 2) * BM + row] = v.z;
            As[(cg * 4 + 3) * BM + row] = v.w;
        }
        // B tile: 16x128 -> Bs[k][n]
#pragma unroll
        for (int s = 0; s < 2; s++) {
            int slot = tid * 2 + s;
            int row = slot >> 5;
            int c4 = slot & 31;
            float4 v = *(const float4*)(B + (size_t)(k0 + row) * ldb + c4 * 4);
            *(float4*)(Bs + row * BN + c4 * 4) = v;
        }
        __syncthreads();
#pragma unroll
        for (int kk = 0; kk < BK; kk++) {
            float ra[TM], rb[TN];
#pragma unroll
            for (int i = 0; i < TM; i += 4)
                *(float4*)&ra[i] = *(const float4*)&As[kk * BM + ty * TM + i];
#pragma unroll
            for (int j = 0; j < TN; j += 4)
                *(float4*)&rb[j] = *(const float4*)&Bs[kk * BN + tx * TN + j];
#pragma unroll
            for (int i = 0; i < TM; i++)
#pragma unroll
                for (int j = 0; j < TN; j++)
                    acc[i][j] = fmaf(ra[i], rb[j], acc[i][j]);
        }
        __syncthreads();
    }
}

// GEMM1: g_H = gelu(X @ W1_e + b1_e)        M=8192 N=2048 K=512
__global__ void __launch_bounds__(256) gemm1_kernel(
    const float* __restrict__ X, const float* __restrict__ W1,
    const float* __restrict__ b1) {
    __shared__ float As[BK * BM];
    __shared__ float Bs[BK * BN];
    int m0 = blockIdx.y * BM;
    int n0 = blockIdx.x * BN;
    float acc[TM][TN];
    sgemm_core(X + (size_t)m0 * DMODEL, DMODEL, W1 + n0, DFF, DMODEL, acc, As, Bs);
    int tx = threadIdx.x & 15, ty = threadIdx.x >> 4;
#pragma unroll
    for (int i = 0; i < TM; i++) {
        int row = m0 + ty * TM + i;
#pragma unroll
        for (int j = 0; j < TN; j++) {
            int col = n0 + tx * TN + j;
            float v = acc[i][j] + b1[col];
            float g = 0.5f * v * (1.0f + erff(v * 0.7071067811865475f));
            g_H[(size_t)row * DFF + col] = g;
        }
    }
}

// GEMM2: out (+)= w_e[row] * (g_H @ W2_e + b2_e)   M=8192 N=512 K=2048
__global__ void __launch_bounds__(256) gemm2_kernel(
    const float* __restrict__ W2, const float* __restrict__ b2,
    float* __restrict__ out, int expert, int first) {
    __shared__ float As[BK * BM];
    __shared__ float Bs[BK * BN];
    int m0 = blockIdx.y * BM;
    int n0 = blockIdx.x * BN;
    float acc[TM][TN];
    sgemm_core(g_H + (size_t)m0 * DFF, DFF, W2 + n0, DMODEL, DFF, acc, As, Bs);
    int tx = threadIdx.x & 15, ty = threadIdx.x >> 4;
#pragma unroll
    for (int i = 0; i < TM; i++) {
        int row = m0 + ty * TM + i;
        float wr = g_w[row * NEXP + expert];
#pragma unroll
        for (int j = 0; j < TN; j++) {
            int col = n0 + tx * TN + j;
            float v = wr * (acc[i][j] + b2[col]);
            size_t oi = (size_t)row * DMODEL + col;
            if (first) out[oi] = v;
            else       out[oi] += v;
        }
    }
}

// ---------------- launch -----------------------------------------------------
extern "C" void kernel_launch(void* const* d_in, const int* in_sizes, int n_in,
                              void* d_out, int out_size) {
    const float* x  = (const float*)d_in[0];
    const float* rw = (const float*)d_in[1];
    const float* W1 = (const float*)d_in[2];
    const float* b1 = (const float*)d_in[3];
    const float* W2 = (const float*)d_in[4];
    const float* b2 = (const float*)d_in[5];
    float* out = (float*)d_out;

    init_kernel<<<1, 32>>>();
    router_kernel<<<NTOK / 8, 256>>>(x, rw);

    dim3 g1(DFF / BN, NTOK / BM);     // (16, 64)
    dim3 g2(DMODEL / BN, NTOK / BM);  // (4, 64)
    for (int e = 0; e < NEXP; e++) {
        gemm1_kernel<<<g1, 256>>>(x, W1 + (size_t)e * DMODEL * DFF, b1 + (size_t)e * DFF);
        gemm2_kernel<<<g2, 256>>>(W2 + (size_t)e * DFF * DMODEL, b2 + (size_t)e * DMODEL,
                                  out, e, e == 0 ? 1 : 0);
    }
    if (out_size > NTOK * DMODEL)
        aux_kernel<<<1, 32>>>(out + (size_t)NTOK * DMODEL);
}

// round 7
// speedup vs baseline: 2.1124x; 2.1124x over previous
#include <cuda_runtime.h>
#include <math.h>

#define NTOK   8192
#define DMODEL 512
#define DFF    2048
#define NEXP   8
#define KMAX   4
#define TOPP   0.9f
#define MAXROWS (KMAX * NTOK)

#define BM 128
#define BN 128
#define BK 16
#define TM 8
#define TN 8

// ---------------- scratch (static device globals; no allocations) ----------
__device__ float g_Hc[(size_t)MAXROWS * DFF];   // 256 MB: compacted gelu(X@W1+b1)
__device__ float g_w[NTOK * NEXP];              // dense combine weights (0 if unselected)
__device__ int   g_idx[NEXP * NTOK];            // per-expert compacted token lists
__device__ int   g_mcnt[NEXP];                  // per-expert token counts
__device__ int   g_off[NEXP];                   // exclusive scan of counts (H row base)
__device__ float g_psum[NEXP];                  // aux: per-expert prob sums

// ---------------- init ------------------------------------------------------
__global__ void init_kernel() {
    int i = threadIdx.x;
    if (i < NEXP) { g_mcnt[i] = 0; g_psum[i] = 0.f; }
}

// ---------------- router: logits + softmax + top-p + compaction + aux -------
// 1 warp per token, 8 warps per block.
__global__ void router_kernel(const float* __restrict__ x,
                              const float* __restrict__ rw) {
    __shared__ float s_rw[DMODEL * NEXP];
    __shared__ float s_psum[NEXP];
    int tid = threadIdx.x;
    if (tid < NEXP) s_psum[tid] = 0.f;
    for (int i = tid; i < DMODEL * NEXP / 4; i += blockDim.x)
        ((float4*)s_rw)[i] = ((const float4*)rw)[i];
    __syncthreads();

    int warp = tid >> 5, lane = tid & 31;
    int t = blockIdx.x * 8 + warp;

    float acc[NEXP];
#pragma unroll
    for (int e = 0; e < NEXP; e++) acc[e] = 0.f;
    const float* xr = x + (size_t)t * DMODEL;
    for (int k = lane; k < DMODEL; k += 32) {
        float xv = xr[k];
        float4 r0 = *(const float4*)&s_rw[k * 8];
        float4 r1 = *(const float4*)&s_rw[k * 8 + 4];
        acc[0] = fmaf(xv, r0.x, acc[0]); acc[1] = fmaf(xv, r0.y, acc[1]);
        acc[2] = fmaf(xv, r0.z, acc[2]); acc[3] = fmaf(xv, r0.w, acc[3]);
        acc[4] = fmaf(xv, r1.x, acc[4]); acc[5] = fmaf(xv, r1.y, acc[5]);
        acc[6] = fmaf(xv, r1.z, acc[6]); acc[7] = fmaf(xv, r1.w, acc[7]);
    }
#pragma unroll
    for (int e = 0; e < NEXP; e++) {
#pragma unroll
        for (int o = 16; o > 0; o >>= 1)
            acc[e] += __shfl_xor_sync(0xffffffffu, acc[e], o);
    }

    if (lane == 0) {
        float mx = acc[0];
#pragma unroll
        for (int e = 1; e < NEXP; e++) mx = fmaxf(mx, acc[e]);
        float p[NEXP]; float s = 0.f;
#pragma unroll
        for (int e = 0; e < NEXP; e++) { p[e] = expf(acc[e] - mx); s += p[e]; }
        float inv = 1.f / s;
#pragma unroll
        for (int e = 0; e < NEXP; e++) p[e] *= inv;
#pragma unroll
        for (int e = 0; e < NEXP; e++) atomicAdd(&s_psum[e], p[e]);

        // top-4 by selection (ties -> lowest index, matches lax.top_k)
        float tmp[NEXP];
#pragma unroll
        for (int e = 0; e < NEXP; e++) tmp[e] = p[e];
        float sp[KMAX]; int si[KMAX];
        for (int j = 0; j < KMAX; j++) {
            float best = tmp[0]; int bi = 0;
            for (int e = 1; e < NEXP; e++)
                if (tmp[e] > best) { best = tmp[e]; bi = e; }
            sp[j] = best; si[j] = bi; tmp[bi] = -1.f;
        }
        // top-p keep: shifted-cumsum < 0.9 OR slot < MIN_EXPERTS(=1)
        float csum = 0.f, wsum = 0.f; bool keep[KMAX];
        for (int j = 0; j < KMAX; j++) {
            keep[j] = (j < 1) || (csum < TOPP);
            csum += sp[j];
            if (keep[j]) wsum += sp[j];
        }
        wsum = fmaxf(wsum, 1e-9f);
        float wout[NEXP];
#pragma unroll
        for (int e = 0; e < NEXP; e++) wout[e] = 0.f;
        for (int j = 0; j < KMAX; j++)
            if (keep[j]) {
                wout[si[j]] = sp[j] / wsum;
                int pos = atomicAdd(&g_mcnt[si[j]], 1);
                g_idx[si[j] * NTOK + pos] = t;
            }
#pragma unroll
        for (int e = 0; e < NEXP; e++) g_w[t * NEXP + e] = wout[e];
    }
    __syncthreads();
    if (tid < NEXP) atomicAdd(&g_psum[tid], s_psum[tid]);
}

// ---------------- scan: exclusive offsets -----------------------------------
__global__ void scan_kernel() {
    if (threadIdx.x == 0) {
        int o = 0;
        for (int e = 0; e < NEXP; e++) { g_off[e] = o; o += g_mcnt[e]; }
    }
}

// ---------------- zero output ------------------------------------------------
__global__ void zero_out_kernel(float* __restrict__ out) {
    size_t i = (size_t)blockIdx.x * blockDim.x + threadIdx.x;
    float4 z = make_float4(0.f, 0.f, 0.f, 0.f);
    ((float4*)out)[i] = z;
}

// ---------------- aux finalize ----------------------------------------------
__global__ void aux_kernel(float* __restrict__ out_aux) {
    if (threadIdx.x == 0) {
        float tot = 0.f;
        for (int e = 0; e < NEXP; e++) tot += (float)g_mcnt[e];
        tot = fmaxf(tot, 1.f);
        float a = 0.f;
        for (int e = 0; e < NEXP; e++)
            a += ((float)g_mcnt[e] / tot) * (g_psum[e] / (float)NTOK);
        *out_aux = 0.01f * (float)NEXP * a;
    }
}

// ---------------- double-buffered SGEMM core --------------------------------
// 128x128 tile, 8x8 regs, 256 threads, 2-stage smem + register prefetch.
__device__ __forceinline__ void tile_compute(const float* __restrict__ As,
                                             const float* __restrict__ Bs,
                                             float acc[TM][TN], int tx, int ty) {
#pragma unroll
    for (int kk = 0; kk < BK; kk++) {
        float ra[TM], rb[TN];
        *(float4*)&ra[0] = *(const float4*)&As[kk * BM + ty * TM];
        *(float4*)&ra[4] = *(const float4*)&As[kk * BM + ty * TM + 4];
        *(float4*)&rb[0] = *(const float4*)&Bs[kk * BN + tx * TN];
        *(float4*)&rb[4] = *(const float4*)&Bs[kk * BN + tx * TN + 4];
#pragma unroll
        for (int i = 0; i < TM; i++)
#pragma unroll
            for (int j = 0; j < TN; j++)
                acc[i][j] = fmaf(ra[i], rb[j], acc[i][j]);
    }
}

template <bool GATHER>
__device__ __forceinline__ void sgemm_db(
    const float* __restrict__ Abase, int lda, const int* __restrict__ s_idx,
    const float* __restrict__ B, int ldb, int K,
    float acc[TM][TN], float* smem) {
    float* As0 = smem;
    float* Bs0 = smem + BK * BM;
    float* As1 = smem + BK * BM + BK * BN;
    float* Bs1 = smem + 2 * BK * BM + BK * BN;

    int tid = threadIdx.x;
#pragma unroll
    for (int i = 0; i < TM; i++)
#pragma unroll
        for (int j = 0; j < TN; j++) acc[i][j] = 0.f;

    int s0 = tid * 2, s1 = tid * 2 + 1;
    int ar0 = s0 >> 2, ac0 = (s0 & 3) * 4;
    int ar1 = s1 >> 2, ac1 = (s1 & 3) * 4;
    int br0 = s0 >> 5, bc0 = (s0 & 31) * 4;
    int br1 = s1 >> 5, bc1 = (s1 & 31) * 4;

    const float* ap0 = Abase + (size_t)(GATHER ? s_idx[ar0] : ar0) * lda + ac0;
    const float* ap1 = Abase + (size_t)(GATHER ? s_idx[ar1] : ar1) * lda + ac1;
    const float* bp0 = B + (size_t)br0 * ldb + bc0;
    const float* bp1 = B + (size_t)br1 * ldb + bc1;

    int tx = tid & 15, ty = tid >> 4;

    float4 ra0 = *(const float4*)ap0;
    float4 ra1 = *(const float4*)ap1;
    float4 rb0 = *(const float4*)bp0;
    float4 rb1 = *(const float4*)bp1;

    // store stage 0
    As0[(ac0 + 0) * BM + ar0] = ra0.x; As0[(ac0 + 1) * BM + ar0] = ra0.y;
    As0[(ac0 + 2) * BM + ar0] = ra0.z; As0[(ac0 + 3) * BM + ar0] = ra0.w;
    As0[(ac1 + 0) * BM + ar1] = ra1.x; As0[(ac1 + 1) * BM + ar1] = ra1.y;
    As0[(ac1 + 2) * BM + ar1] = ra1.z; As0[(ac1 + 3) * BM + ar1] = ra1.w;
    *(float4*)&Bs0[br0 * BN + bc0] = rb0;
    *(float4*)&Bs0[br1 * BN + bc1] = rb1;
    __syncthreads();

    int T = K / BK;
    for (int t = 0; t < T; t++) {
        const float* As = (t & 1) ? As1 : As0;
        const float* Bs = (t & 1) ? Bs1 : Bs0;
        if (t + 1 < T) {
            int k = (t + 1) * BK;
            ra0 = *(const float4*)(ap0 + k);
            ra1 = *(const float4*)(ap1 + k);
            rb0 = *(const float4*)(bp0 + (size_t)k * ldb);
            rb1 = *(const float4*)(bp1 + (size_t)k * ldb);
        }
        tile_compute(As, Bs, acc, tx, ty);
        if (t + 1 < T) {
            float* Asn = (t & 1) ? As0 : As1;
            float* Bsn = (t & 1) ? Bs0 : Bs1;
            Asn[(ac0 + 0) * BM + ar0] = ra0.x; Asn[(ac0 + 1) * BM + ar0] = ra0.y;
            Asn[(ac0 + 2) * BM + ar0] = ra0.z; Asn[(ac0 + 3) * BM + ar0] = ra0.w;
            Asn[(ac1 + 0) * BM + ar1] = ra1.x; Asn[(ac1 + 1) * BM + ar1] = ra1.y;
            Asn[(ac1 + 2) * BM + ar1] = ra1.z; Asn[(ac1 + 3) * BM + ar1] = ra1.w;
            *(float4*)&Bsn[br0 * BN + bc0] = rb0;
            *(float4*)&Bsn[br1 * BN + bc1] = rb1;
        }
        __syncthreads();
    }
}

// GEMM1 (batched over experts): g_Hc[off_e + i] = gelu(X[idx] @ W1_e + b1_e)
__global__ void __launch_bounds__(256, 2) gemm1_kernel(
    const float* __restrict__ X, const float* __restrict__ W1,
    const float* __restrict__ b1) {
    int e = blockIdx.z;
    int m_e = g_mcnt[e];
    int m0 = blockIdx.y * BM;
    if (m0 >= m_e) return;

    __shared__ float smem[4 * BK * BM];
    __shared__ int s_idx[BM];
    int tid = threadIdx.x;
    if (tid < BM) {
        int r = m0 + tid;
        s_idx[tid] = g_idx[e * NTOK + (r < m_e ? r : m_e - 1)];
    }
    __syncthreads();

    int n0 = blockIdx.x * BN;
    float acc[TM][TN];
    sgemm_db<true>(X, DMODEL, s_idx,
                   W1 + (size_t)e * DMODEL * DFF + n0, DFF, DMODEL, acc, smem);

    int tx = tid & 15, ty = tid >> 4;
    const float* b1e = b1 + e * DFF + n0 + tx * TN;
    float bcol[TN];
#pragma unroll
    for (int j = 0; j < TN; j++) bcol[j] = b1e[j];

    int off = g_off[e];
#pragma unroll
    for (int i = 0; i < TM; i++) {
        int lr = ty * TM + i;
        if (m0 + lr < m_e) {
            float* hrow = g_Hc + (size_t)(off + m0 + lr) * DFF + n0 + tx * TN;
#pragma unroll
            for (int j = 0; j < TN; j++) {
                float v = acc[i][j] + bcol[j];
                hrow[j] = 0.5f * v * (1.0f + erff(v * 0.7071067811865475f));
            }
        }
    }
}

// GEMM2 (per expert, sequential): out[token] += w * (H @ W2_e + b2_e)
__global__ void __launch_bounds__(256, 2) gemm2_kernel(
    const float* __restrict__ W2, const float* __restrict__ b2,
    float* __restrict__ out, int e) {
    int m_e = g_mcnt[e];
    int m0 = blockIdx.y * BM;
    if (m0 >= m_e) return;

    __shared__ float smem[4 * BK * BM];
    __shared__ int s_idx[BM];
    int tid = threadIdx.x;
    if (tid < BM) {
        int r = m0 + tid;
        s_idx[tid] = g_idx[e * NTOK + (r < m_e ? r : m_e - 1)];
    }
    __syncthreads();

    int n0 = blockIdx.x * BN;
    int off = g_off[e];
    float acc[TM][TN];
    sgemm_db<false>(g_Hc + (size_t)(off + m0) * DFF, DFF, nullptr,
                    W2 + (size_t)e * DFF * DMODEL + n0, DMODEL, DFF, acc, smem);

    int tx = tid & 15, ty = tid >> 4;
    const float* b2e = b2 + e * DMODEL + n0 + tx * TN;
    float bcol[TN];
#pragma unroll
    for (int j = 0; j < TN; j++) bcol[j] = b2e[j];

#pragma unroll
    for (int i = 0; i < TM; i++) {
        int lr = ty * TM + i;
        if (m0 + lr < m_e) {
            int tok = s_idx[lr];
            float w = g_w[tok * NEXP + e];
            float* orow = out + (size_t)tok * DMODEL + n0 + tx * TN;
            float4 o0 = *(float4*)&orow[0];
            float4 o1 = *(float4*)&orow[4];
            o0.x += w * (acc[i][0] + bcol[0]);
            o0.y += w * (acc[i][1] + bcol[1]);
            o0.z += w * (acc[i][2] + bcol[2]);
            o0.w += w * (acc[i][3] + bcol[3]);
            o1.x += w * (acc[i][4] + bcol[4]);
            o1.y += w * (acc[i][5] + bcol[5]);
            o1.z += w * (acc[i][6] + bcol[6]);
            o1.w += w * (acc[i][7] + bcol[7]);
            *(float4*)&orow[0] = o0;
            *(float4*)&orow[4] = o1;
        }
    }
}

// ---------------- launch -----------------------------------------------------
extern "C" void kernel_launch(void* const* d_in, const int* in_sizes, int n_in,
                              void* d_out, int out_size) {
    const float* x  = (const float*)d_in[0];
    const float* rw = (const float*)d_in[1];
    const float* W1 = (const float*)d_in[2];
    const float* b1 = (const float*)d_in[3];
    const float* W2 = (const float*)d_in[4];
    const float* b2 = (const float*)d_in[5];
    float* out = (float*)d_out;

    init_kernel<<<1, 32>>>();
    router_kernel<<<NTOK / 8, 256>>>(x, rw);
    scan_kernel<<<1, 32>>>();
    zero_out_kernel<<<NTOK * DMODEL / 4 / 256, 256>>>(out);

    dim3 g1(DFF / BN, NTOK / BM, NEXP);   // (16, 64, 8), half early-exit
    gemm1_kernel<<<g1, 256>>>(x, W1, b1);

    dim3 g2(DMODEL / BN, NTOK / BM);      // (4, 64), half early-exit
    for (int e = 0; e < NEXP; e++)
        gemm2_kernel<<<g2, 256>>>(W2, b2, out, e);

    if (out_size > NTOK * DMODEL)
        aux_kernel<<<1, 32>>>(out + (size_t)NTOK * DMODEL);
}

// round 12
// speedup vs baseline: 3.8895x; 1.8413x over previous
#include <cuda_runtime.h>
#include <cuda_bf16.h>
#include <math.h>
#include <stdint.h>

#define NTOK   8192
#define DMODEL 512
#define DFF    2048
#define NEXP   8
#define KMAX   4
#define TOPP   0.9f
#define MAXROWS (KMAX * NTOK)

#define BM 128
#define BN 128
#define BKT 32            // k per smem stage (bf16 elems)
#define APAD_B 80         // padded bytes per 32-elem bf16 row (64 data + 16 pad)
#define TERM_B (128 * APAD_B)      // 10240 bytes per term tile
#define STAGE_B (4 * TERM_B)       // Ah, Al, Bh, Bl
#define DYN_SMEM (2 * STAGE_B)     // 81920

// ---------------- device scratch (static; no allocations) -------------------
__device__ __align__(16) __nv_bfloat16 g_Xh[NTOK * DMODEL];
__device__ __align__(16) __nv_bfloat16 g_Xl[NTOK * DMODEL];
__device__ __align__(16) __nv_bfloat16 g_W1tH[NEXP * DFF * DMODEL];  // [e][n][k]
__device__ __align__(16) __nv_bfloat16 g_W1tL[NEXP * DFF * DMODEL];
__device__ __align__(16) __nv_bfloat16 g_W2tH[NEXP * DMODEL * DFF];  // [e][n][k]
__device__ __align__(16) __nv_bfloat16 g_W2tL[NEXP * DMODEL * DFF];
__device__ __align__(16) __nv_bfloat16 g_HH[(size_t)MAXROWS * DFF];
__device__ __align__(16) __nv_bfloat16 g_HL[(size_t)MAXROWS * DFF];
__device__ __align__(16) float g_P[(size_t)MAXROWS * DMODEL];
__device__ int   g_idx[NEXP * NTOK];
__device__ int   g_sel_e[NTOK * KMAX];
__device__ int   g_sel_pos[NTOK * KMAX];
__device__ float g_sel_w[NTOK * KMAX];
__device__ int   g_mcnt[NEXP];
__device__ int   g_off[NEXP];
__device__ float g_psum[NEXP];

// ---------------- helpers -----------------------------------------------------
__device__ __forceinline__ void mma16816(float* c, const uint32_t a[4],
                                         uint32_t b0, uint32_t b1) {
    asm volatile(
        "mma.sync.aligned.m16n8k16.row.col.f32.bf16.bf16.f32 "
        "{%0,%1,%2,%3}, {%4,%5,%6,%7}, {%8,%9}, {%0,%1,%2,%3};"
        : "+f"(c[0]), "+f"(c[1]), "+f"(c[2]), "+f"(c[3])
        : "r"(a[0]), "r"(a[1]), "r"(a[2]), "r"(a[3]), "r"(b0), "r"(b1));
}

__device__ __forceinline__ void bsplit(float x, __nv_bfloat16& h, __nv_bfloat16& l) {
    h = __float2bfloat16(x);
    l = __float2bfloat16(x - __bfloat162float(h));
}

// ---------------- init / router / scan / aux --------------------------------
__global__ void init_kernel() {
    int i = threadIdx.x;
    if (i < NEXP) { g_mcnt[i] = 0; g_psum[i] = 0.f; }
}

__global__ void router_kernel(const float* __restrict__ x,
                              const float* __restrict__ rw) {
    __shared__ float s_rw[DMODEL * NEXP];
    __shared__ float s_psum[NEXP];
    int tid = threadIdx.x;
    if (tid < NEXP) s_psum[tid] = 0.f;
    for (int i = tid; i < DMODEL * NEXP / 4; i += blockDim.x)
        ((float4*)s_rw)[i] = ((const float4*)rw)[i];
    __syncthreads();

    int warp = tid >> 5, lane = tid & 31;
    int t = blockIdx.x * 8 + warp;

    float acc[NEXP];
#pragma unroll
    for (int e = 0; e < NEXP; e++) acc[e] = 0.f;
    const float* xr = x + (size_t)t * DMODEL;
    for (int k = lane; k < DMODEL; k += 32) {
        float xv = xr[k];
        float4 r0 = *(const float4*)&s_rw[k * 8];
        float4 r1 = *(const float4*)&s_rw[k * 8 + 4];
        acc[0] = fmaf(xv, r0.x, acc[0]); acc[1] = fmaf(xv, r0.y, acc[1]);
        acc[2] = fmaf(xv, r0.z, acc[2]); acc[3] = fmaf(xv, r0.w, acc[3]);
        acc[4] = fmaf(xv, r1.x, acc[4]); acc[5] = fmaf(xv, r1.y, acc[5]);
        acc[6] = fmaf(xv, r1.z, acc[6]); acc[7] = fmaf(xv, r1.w, acc[7]);
    }
#pragma unroll
    for (int e = 0; e < NEXP; e++) {
#pragma unroll
        for (int o = 16; o > 0; o >>= 1)
            acc[e] += __shfl_xor_sync(0xffffffffu, acc[e], o);
    }

    if (lane == 0) {
        float mx = acc[0];
#pragma unroll
        for (int e = 1; e < NEXP; e++) mx = fmaxf(mx, acc[e]);
        float p[NEXP]; float s = 0.f;
#pragma unroll
        for (int e = 0; e < NEXP; e++) { p[e] = expf(acc[e] - mx); s += p[e]; }
        float inv = 1.f / s;
#pragma unroll
        for (int e = 0; e < NEXP; e++) p[e] *= inv;
#pragma unroll
        for (int e = 0; e < NEXP; e++) atomicAdd(&s_psum[e], p[e]);

        float tmp[NEXP];
#pragma unroll
        for (int e = 0; e < NEXP; e++) tmp[e] = p[e];
        float sp[KMAX]; int si[KMAX];
        for (int j = 0; j < KMAX; j++) {
            float best = tmp[0]; int bi = 0;
            for (int e = 1; e < NEXP; e++)
                if (tmp[e] > best) { best = tmp[e]; bi = e; }
            sp[j] = best; si[j] = bi; tmp[bi] = -1.f;
        }
        float csum = 0.f, wsum = 0.f; bool keep[KMAX];
        for (int j = 0; j < KMAX; j++) {
            keep[j] = (j < 1) || (csum < TOPP);
            csum += sp[j];
            if (keep[j]) wsum += sp[j];
        }
        wsum = fmaxf(wsum, 1e-9f);
        for (int j = 0; j < KMAX; j++) g_sel_e[t * KMAX + j] = -1;
        for (int j = 0; j < KMAX; j++)
            if (keep[j]) {
                int pos = atomicAdd(&g_mcnt[si[j]], 1);
                g_idx[si[j] * NTOK + pos] = t;
                g_sel_e[t * KMAX + j]   = si[j];
                g_sel_pos[t * KMAX + j] = pos;
                g_sel_w[t * KMAX + j]   = sp[j] / wsum;
            }
    }
    __syncthreads();
    if (tid < NEXP) atomicAdd(&g_psum[tid], s_psum[tid]);
}

__global__ void scan_kernel() {
    if (threadIdx.x == 0) {
        int o = 0;
        for (int e = 0; e < NEXP; e++) { g_off[e] = o; o += g_mcnt[e]; }
    }
}

__global__ void aux_kernel(float* __restrict__ out_aux) {
    if (threadIdx.x == 0) {
        float tot = 0.f;
        for (int e = 0; e < NEXP; e++) tot += (float)g_mcnt[e];
        tot = fmaxf(tot, 1.f);
        float a = 0.f;
        for (int e = 0; e < NEXP; e++)
            a += ((float)g_mcnt[e] / tot) * (g_psum[e] / (float)NTOK);
        *out_aux = 0.01f * (float)NEXP * a;
    }
}

// ---------------- bf16 split pre-passes --------------------------------------
__global__ void convx_kernel(const float* __restrict__ x) {
    int i = blockIdx.x * blockDim.x + threadIdx.x;   // float4 index
    float4 v = ((const float4*)x)[i];
    __nv_bfloat16 h0, l0, h1, l1, h2, l2, h3, l3;
    bsplit(v.x, h0, l0); bsplit(v.y, h1, l1);
    bsplit(v.z, h2, l2); bsplit(v.w, h3, l3);
    __nv_bfloat162* ph = (__nv_bfloat162*)g_Xh;
    __nv_bfloat162* pl = (__nv_bfloat162*)g_Xl;
    ph[i * 2]     = __nv_bfloat162{h0, h1};
    ph[i * 2 + 1] = __nv_bfloat162{h2, h3};
    pl[i * 2]     = __nv_bfloat162{l0, l1};
    pl[i * 2 + 1] = __nv_bfloat162{l2, l3};
}

// in[z][R][C] fp32 -> out[z][C][R] bf16 hi/lo.  which: 0 -> W1t, 1 -> W2t
__global__ void transpose_split_kernel(const float* __restrict__ in, int which,
                                       int R, int C) {
    __shared__ float tile[32][33];
    __nv_bfloat16* outH = which ? g_W2tH : g_W1tH;
    __nv_bfloat16* outL = which ? g_W2tL : g_W1tL;
    int z = blockIdx.z;
    const float* src = in + (size_t)z * R * C;
    int c0 = blockIdx.x * 32, r0 = blockIdx.y * 32;
    int tx = threadIdx.x, ty = threadIdx.y;
#pragma unroll
    for (int j = 0; j < 32; j += 8)
        tile[ty + j][tx] = src[(size_t)(r0 + ty + j) * C + c0 + tx];
    __syncthreads();
    size_t ob = (size_t)z * R * C;
#pragma unroll
    for (int j = 0; j < 32; j += 8) {
        float v = tile[tx][ty + j];
        __nv_bfloat16 h, l;
        bsplit(v, h, l);
        size_t o = ob + (size_t)(c0 + ty + j) * R + r0 + tx;
        outH[o] = h;
        outL[o] = l;
    }
}

// ---------------- bf16x3 MMA compute for one 128x128x32 k-tile ---------------
__device__ __forceinline__ void compute_ktile(const char* sbase,
                                              float acc[2][8][4],
                                              int aoff, int boff) {
#pragma unroll
    for (int ks = 0; ks < 2; ks++) {
        int kb = ks * 32;                      // 16 bf16 = 32 bytes
        uint32_t ah[2][4], al[2][4];
#pragma unroll
        for (int mt = 0; mt < 2; mt++) {
            const char* pa = sbase + aoff + mt * (16 * APAD_B) + kb;
            ah[mt][0] = *(const uint32_t*)(pa);
            ah[mt][1] = *(const uint32_t*)(pa + 8 * APAD_B);
            ah[mt][2] = *(const uint32_t*)(pa + 16);
            ah[mt][3] = *(const uint32_t*)(pa + 8 * APAD_B + 16);
            const char* pl = pa + TERM_B;
            al[mt][0] = *(const uint32_t*)(pl);
            al[mt][1] = *(const uint32_t*)(pl + 8 * APAD_B);
            al[mt][2] = *(const uint32_t*)(pl + 16);
            al[mt][3] = *(const uint32_t*)(pl + 8 * APAD_B + 16);
        }
#pragma unroll
        for (int nt = 0; nt < 8; nt++) {
            const char* pb = sbase + 2 * TERM_B + boff + nt * (8 * APAD_B) + kb;
            uint32_t bh0 = *(const uint32_t*)(pb);
            uint32_t bh1 = *(const uint32_t*)(pb + 16);
            uint32_t bl0 = *(const uint32_t*)(pb + TERM_B);
            uint32_t bl1 = *(const uint32_t*)(pb + TERM_B + 16);
#pragma unroll
            for (int mt = 0; mt < 2; mt++) {
                mma16816(acc[mt][nt], ah[mt], bh0, bh1);
                mma16816(acc[mt][nt], ah[mt], bl0, bl1);
                mma16816(acc[mt][nt], al[mt], bh0, bh1);
            }
        }
    }
}

// GEMM1: H(hi/lo bf16) = gelu(X[idx] @ W1_e + b1_e), all experts batched
__global__ void __launch_bounds__(256) gemm1_mma(const float* __restrict__ b1) {
    int e = blockIdx.z;
    int m_e = g_mcnt[e];
    int m0 = blockIdx.y * BM;
    if (m0 >= m_e) return;
    int n0 = blockIdx.x * BN;

    extern __shared__ char smem[];
    __shared__ int s_idx[BM];

    int tid = threadIdx.x;
    if (tid < BM) {
        int r = m0 + tid;
        s_idx[tid] = g_idx[e * NTOK + (r < m_e ? r : m_e - 1)];
    }
    __syncthreads();

    // copy-lane assignment: 2 slots, slot -> (row, c4)
    int r0s = (tid * 2) >> 2,     c40 = (tid * 2) & 3;
    int r1s = (tid * 2 + 1) >> 2, c41 = (tid * 2 + 1) & 3;
    const char* aH0 = (const char*)(g_Xh + (size_t)s_idx[r0s] * DMODEL) + c40 * 16;
    const char* aH1 = (const char*)(g_Xh + (size_t)s_idx[r1s] * DMODEL) + c41 * 16;
    const char* aL0 = (const char*)(g_Xl + (size_t)s_idx[r0s] * DMODEL) + c40 * 16;
    const char* aL1 = (const char*)(g_Xl + (size_t)s_idx[r1s] * DMODEL) + c41 * 16;
    const char* bH0 = (const char*)(g_W1tH + ((size_t)e * DFF + n0 + r0s) * DMODEL) + c40 * 16;
    const char* bH1 = (const char*)(g_W1tH + ((size_t)e * DFF + n0 + r1s) * DMODEL) + c41 * 16;
    const char* bL0 = (const char*)(g_W1tL + ((size_t)e * DFF + n0 + r0s) * DMODEL) + c40 * 16;
    const char* bL1 = (const char*)(g_W1tL + ((size_t)e * DFF + n0 + r1s) * DMODEL) + c41 * 16;
    int so0 = r0s * APAD_B + c40 * 16;
    int so1 = r1s * APAD_B + c41 * 16;

    int wid = tid >> 5, lane = tid & 31;
    int warp_m = wid & 3, warp_n = wid >> 2;
    int qid = lane >> 2, qp = lane & 3;
    int aoff = (warp_m * 32 + qid) * APAD_B + qp * 4;
    int boff = (warp_n * 64 + qid) * APAD_B + qp * 4;

    float acc[2][8][4];
#pragma unroll
    for (int mt = 0; mt < 2; mt++)
#pragma unroll
        for (int nt = 0; nt < 8; nt++)
#pragma unroll
            for (int q = 0; q < 4; q++) acc[mt][nt][q] = 0.f;

    // stage 0
    {
        char* s = smem;
        *(float4*)(s + so0) = *(const float4*)aH0;
        *(float4*)(s + so1) = *(const float4*)aH1;
        *(float4*)(s + TERM_B + so0) = *(const float4*)aL0;
        *(float4*)(s + TERM_B + so1) = *(const float4*)aL1;
        *(float4*)(s + 2 * TERM_B + so0) = *(const float4*)bH0;
        *(float4*)(s + 2 * TERM_B + so1) = *(const float4*)bH1;
        *(float4*)(s + 3 * TERM_B + so0) = *(const float4*)bL0;
        *(float4*)(s + 3 * TERM_B + so1) = *(const float4*)bL1;
    }
    __syncthreads();

    const int T = DMODEL / BKT;   // 16
    for (int t = 0; t < T; t++) {
        float4 va0, va1, vl0, vl1, vb0, vb1, vc0, vc1;
        if (t + 1 < T) {
            int kB = (t + 1) * 64;   // 32 bf16 = 64 bytes
            va0 = *(const float4*)(aH0 + kB); va1 = *(const float4*)(aH1 + kB);
            vl0 = *(const float4*)(aL0 + kB); vl1 = *(const float4*)(aL1 + kB);
            vb0 = *(const float4*)(bH0 + kB); vb1 = *(const float4*)(bH1 + kB);
            vc0 = *(const float4*)(bL0 + kB); vc1 = *(const float4*)(bL1 + kB);
        }
        compute_ktile(smem + (t & 1) * STAGE_B, acc, aoff, boff);
        if (t + 1 < T) {
            char* s = smem + ((t + 1) & 1) * STAGE_B;
            *(float4*)(s + so0) = va0;
            *(float4*)(s + so1) = va1;
            *(float4*)(s + TERM_B + so0) = vl0;
            *(float4*)(s + TERM_B + so1) = vl1;
            *(float4*)(s + 2 * TERM_B + so0) = vb0;
            *(float4*)(s + 2 * TERM_B + so1) = vb1;
            *(float4*)(s + 3 * TERM_B + so0) = vc0;
            *(float4*)(s + 3 * TERM_B + so1) = vc1;
        }
        __syncthreads();
    }

    // epilogue: gelu + bf16 split -> g_HH / g_HL
    int off = g_off[e];
    float2 bv[8];
    const float* b1p = b1 + e * DFF + n0 + warp_n * 64 + qp * 2;
#pragma unroll
    for (int nt = 0; nt < 8; nt++)
        bv[nt] = *(const float2*)(b1p + nt * 8);

#pragma unroll
    for (int mt = 0; mt < 2; mt++) {
#pragma unroll
        for (int half = 0; half < 2; half++) {
            int rl = warp_m * 32 + mt * 16 + half * 8 + qid;
            if (m0 + rl < m_e) {
                size_t rb = (size_t)(off + m0 + rl) * DFF;
#pragma unroll
                for (int nt = 0; nt < 8; nt++) {
                    int col = n0 + warp_n * 64 + nt * 8 + qp * 2;
                    float v0 = acc[mt][nt][half * 2 + 0] + bv[nt].x;
                    float v1 = acc[mt][nt][half * 2 + 1] + bv[nt].y;
                    float gg0 = 0.5f * v0 * (1.0f + erff(v0 * 0.7071067811865475f));
                    float gg1 = 0.5f * v1 * (1.0f + erff(v1 * 0.7071067811865475f));
                    __nv_bfloat16 h0, l0, h1, l1;
                    bsplit(gg0, h0, l0);
                    bsplit(gg1, h1, l1);
                    *(__nv_bfloat162*)(g_HH + rb + col) = __nv_bfloat162{h0, h1};
                    *(__nv_bfloat162*)(g_HL + rb + col) = __nv_bfloat162{l0, l1};
                }
            }
        }
    }
}

// GEMM2: g_P = H @ W2_e + b2_e (per-expert partial rows, all experts batched)
__global__ void __launch_bounds__(256) gemm2_mma(const float* __restrict__ b2) {
    int e = blockIdx.z;
    int m_e = g_mcnt[e];
    int m0 = blockIdx.y * BM;
    if (m0 >= m_e) return;
    int n0 = blockIdx.x * BN;
    int off = g_off[e];

    extern __shared__ char smem[];
    int tid = threadIdx.x;

    int r0s = (tid * 2) >> 2,     c40 = (tid * 2) & 3;
    int r1s = (tid * 2 + 1) >> 2, c41 = (tid * 2 + 1) & 3;
    int rr0 = m0 + r0s; if (rr0 >= m_e) rr0 = m_e - 1;
    int rr1 = m0 + r1s; if (rr1 >= m_e) rr1 = m_e - 1;
    const char* aH0 = (const char*)(g_HH + (size_t)(off + rr0) * DFF) + c40 * 16;
    const char* aH1 = (const char*)(g_HH + (size_t)(off + rr1) * DFF) + c41 * 16;
    const char* aL0 = (const char*)(g_HL + (size_t)(off + rr0) * DFF) + c40 * 16;
    const char* aL1 = (const char*)(g_HL + (size_t)(off + rr1) * DFF) + c41 * 16;
    const char* bH0 = (const char*)(g_W2tH + ((size_t)e * DMODEL + n0 + r0s) * DFF) + c40 * 16;
    const char* bH1 = (const char*)(g_W2tH + ((size_t)e * DMODEL + n0 + r1s) * DFF) + c41 * 16;
    const char* bL0 = (const char*)(g_W2tL + ((size_t)e * DMODEL + n0 + r0s) * DFF) + c40 * 16;
    const char* bL1 = (const char*)(g_W2tL + ((size_t)e * DMODEL + n0 + r1s) * DFF) + c41 * 16;
    int so0 = r0s * APAD_B + c40 * 16;
    int so1 = r1s * APAD_B + c41 * 16;

    int wid = tid >> 5, lane = tid & 31;
    int warp_m = wid & 3, warp_n = wid >> 2;
    int qid = lane >> 2, qp = lane & 3;
    int aoff = (warp_m * 32 + qid) * APAD_B + qp * 4;
    int boff = (warp_n * 64 + qid) * APAD_B + qp * 4;

    float acc[2][8][4];
#pragma unroll
    for (int mt = 0; mt < 2; mt++)
#pragma unroll
        for (int nt = 0; nt < 8; nt++)
#pragma unroll
            for (int q = 0; q < 4; q++) acc[mt][nt][q] = 0.f;

    {
        char* s = smem;
        *(float4*)(s + so0) = *(const float4*)aH0;
        *(float4*)(s + so1) = *(const float4*)aH1;
        *(float4*)(s + TERM_B + so0) = *(const float4*)aL0;
        *(float4*)(s + TERM_B + so1) = *(const float4*)aL1;
        *(float4*)(s + 2 * TERM_B + so0) = *(const float4*)bH0;
        *(float4*)(s + 2 * TERM_B + so1) = *(const float4*)bH1;
        *(float4*)(s + 3 * TERM_B + so0) = *(const float4*)bL0;
        *(float4*)(s + 3 * TERM_B + so1) = *(const float4*)bL1;
    }
    __syncthreads();

    const int T = DFF / BKT;   // 64
    for (int t = 0; t < T; t++) {
        float4 va0, va1, vl0, vl1, vb0, vb1, vc0, vc1;
        if (t + 1 < T) {
            int kB = (t + 1) * 64;
            va0 = *(const float4*)(aH0 + kB); va1 = *(const float4*)(aH1 + kB);
            vl0 = *(const float4*)(aL0 + kB); vl1 = *(const float4*)(aL1 + kB);
            vb0 = *(const float4*)(bH0 + kB); vb1 = *(const float4*)(bH1 + kB);
            vc0 = *(const float4*)(bL0 + kB); vc1 = *(const float4*)(bL1 + kB);
        }
        compute_ktile(smem + (t & 1) * STAGE_B, acc, aoff, boff);
        if (t + 1 < T) {
            char* s = smem + ((t + 1) & 1) * STAGE_B;
            *(float4*)(s + so0) = va0;
            *(float4*)(s + so1) = va1;
            *(float4*)(s + TERM_B + so0) = vl0;
            *(float4*)(s + TERM_B + so1) = vl1;
            *(float4*)(s + 2 * TERM_B + so0) = vb0;
            *(float4*)(s + 2 * TERM_B + so1) = vb1;
            *(float4*)(s + 3 * TERM_B + so0) = vc0;
            *(float4*)(s + 3 * TERM_B + so1) = vc1;
        }
        __syncthreads();
    }

    // epilogue: + b2 -> fp32 partials g_P
    float2 bv[8];
    const float* b2p = b2 + e * DMODEL + n0 + warp_n * 64 + qp * 2;
#pragma unroll
    for (int nt = 0; nt < 8; nt++)
        bv[nt] = *(const float2*)(b2p + nt * 8);

#pragma unroll
    for (int mt = 0; mt < 2; mt++) {
#pragma unroll
        for (int half = 0; half < 2; half++) {
            int rl = warp_m * 32 + mt * 16 + half * 8 + qid;
            if (m0 + rl < m_e) {
                size_t rb = (size_t)(off + m0 + rl) * DMODEL;
#pragma unroll
                for (int nt = 0; nt < 8; nt++) {
                    int col = n0 + warp_n * 64 + nt * 8 + qp * 2;
                    float2 v;
                    v.x = acc[mt][nt][half * 2 + 0] + bv[nt].x;
                    v.y = acc[mt][nt][half * 2 + 1] + bv[nt].y;
                    *(float2*)(g_P + rb + col) = v;
                }
            }
        }
    }
}

// ---------------- combine: out[tok] = sum_j w_j * P[row_j] -------------------
__global__ void combine_kernel(float* __restrict__ out) {
    int tok = blockIdx.x;
    int c = threadIdx.x * 4;
    float4 acc = make_float4(0.f, 0.f, 0.f, 0.f);
#pragma unroll
    for (int j = 0; j < KMAX; j++) {
        int e = g_sel_e[tok * KMAX + j];
        if (e >= 0) {
            float w = g_sel_w[tok * KMAX + j];
            int row = g_off[e] + g_sel_pos[tok * KMAX + j];
            float4 p = *(const float4*)(g_P + (size_t)row * DMODEL + c);
            acc.x += w * p.x; acc.y += w * p.y;
            acc.z += w * p.z; acc.w += w * p.w;
        }
    }
    *(float4*)(out + (size_t)tok * DMODEL + c) = acc;
}

// ---------------- launch ------------------------------------------------------
extern "C" void kernel_launch(void* const* d_in, const int* in_sizes, int n_in,
                              void* d_out, int out_size) {
    const float* x  = (const float*)d_in[0];
    const float* rw = (const float*)d_in[1];
    const float* W1 = (const float*)d_in[2];
    const float* b1 = (const float*)d_in[3];
    const float* W2 = (const float*)d_in[4];
    const float* b2 = (const float*)d_in[5];
    float* out = (float*)d_out;

    cudaFuncSetAttribute(gemm1_mma, cudaFuncAttributeMaxDynamicSharedMemorySize, DYN_SMEM);
    cudaFuncSetAttribute(gemm2_mma, cudaFuncAttributeMaxDynamicSharedMemorySize, DYN_SMEM);

    init_kernel<<<1, 32>>>();
    router_kernel<<<NTOK / 8, 256>>>(x, rw);
    scan_kernel<<<1, 32>>>();

    convx_kernel<<<NTOK * DMODEL / 4 / 256, 256>>>(x);
    transpose_split_kernel<<<dim3(DFF / 32, DMODEL / 32, NEXP), dim3(32, 8)>>>(
        W1, 0, DMODEL, DFF);
    transpose_split_kernel<<<dim3(DMODEL / 32, DFF / 32, NEXP), dim3(32, 8)>>>(
        W2, 1, DFF, DMODEL);

    gemm1_mma<<<dim3(DFF / BN, NTOK / BM, NEXP), 256, DYN_SMEM>>>(b1);
    gemm2_mma<<<dim3(DMODEL / BN, NTOK / BM, NEXP), 256, DYN_SMEM>>>(b2);

    combine_kernel<<<NTOK, 128>>>(out);

    if (out_size > NTOK * DMODEL)
        aux_kernel<<<1, 32>>>(out + (size_t)NTOK * DMODEL);
}

// round 15
// speedup vs baseline: 5.0406x; 1.2959x over previous
#include <cuda_runtime.h>
#include <cuda_bf16.h>
#include <math.h>
#include <stdint.h>

#define NTOK   8192
#define DMODEL 512
#define DFF    2048
#define NEXP   8
#define KMAX   4
#define TOPP   0.9f
#define MAXROWS (KMAX * NTOK)

#define BM 128
#define BN 128
#define BKT 32            // k per smem stage (bf16 elems)
#define APAD_B 80         // padded bytes per 32-elem bf16 row (64 data + 16 pad)
#define TERM_B (128 * APAD_B)      // 10240 bytes per term tile
#define STAGE_B (4 * TERM_B)       // Ah, Al, Bh, Bl
#define DYN_SMEM (2 * STAGE_B)     // 81920

// ---------------- device scratch (static; no allocations) -------------------
__device__ __align__(16) __nv_bfloat16 g_Xh[NTOK * DMODEL];
__device__ __align__(16) __nv_bfloat16 g_Xl[NTOK * DMODEL];
__device__ __align__(16) __nv_bfloat16 g_W1tH[NEXP * DFF * DMODEL];  // [e][n][k]
__device__ __align__(16) __nv_bfloat16 g_W1tL[NEXP * DFF * DMODEL];
__device__ __align__(16) __nv_bfloat16 g_W2tH[NEXP * DMODEL * DFF];  // [e][n][k]
__device__ __align__(16) __nv_bfloat16 g_W2tL[NEXP * DMODEL * DFF];
__device__ __align__(16) __nv_bfloat16 g_HH[(size_t)MAXROWS * DFF];
__device__ __align__(16) __nv_bfloat16 g_HL[(size_t)MAXROWS * DFF];
__device__ __align__(16) float g_P[(size_t)MAXROWS * DMODEL];
__device__ int   g_idx[NEXP * NTOK];
__device__ int   g_sel_e[NTOK * KMAX];
__device__ int   g_sel_pos[NTOK * KMAX];
__device__ float g_sel_w[NTOK * KMAX];
__device__ int   g_mcnt[NEXP];
__device__ int   g_off[NEXP];
__device__ float g_psum[NEXP];

// ---------------- helpers -----------------------------------------------------
__device__ __forceinline__ uint32_t smem_u32(const void* p) {
    uint32_t a;
    asm("{ .reg .u64 t; cvta.to.shared.u64 t, %1; cvt.u32.u64 %0, t; }"
        : "=r"(a) : "l"(p));
    return a;
}
__device__ __forceinline__ void mma16816(float* c, const uint32_t a[4],
                                         uint32_t b0, uint32_t b1) {
    asm volatile(
        "mma.sync.aligned.m16n8k16.row.col.f32.bf16.bf16.f32 "
        "{%0,%1,%2,%3}, {%4,%5,%6,%7}, {%8,%9}, {%0,%1,%2,%3};"
        : "+f"(c[0]), "+f"(c[1]), "+f"(c[2]), "+f"(c[3])
        : "r"(a[0]), "r"(a[1]), "r"(a[2]), "r"(a[3]), "r"(b0), "r"(b1));
}
__device__ __forceinline__ void ldsm4(uint32_t* r, uint32_t addr) {
    asm volatile("ldmatrix.sync.aligned.m8n8.x4.shared.b16 {%0,%1,%2,%3}, [%4];"
        : "=r"(r[0]), "=r"(r[1]), "=r"(r[2]), "=r"(r[3]) : "r"(addr));
}
__device__ __forceinline__ void cpasync16(uint32_t dst, const void* src) {
    asm volatile("cp.async.cg.shared.global [%0], [%1], 16;"
        :: "r"(dst), "l"(src) : "memory");
}
#define CP_COMMIT() asm volatile("cp.async.commit_group;" ::: "memory")
#define CP_WAIT(n)  asm volatile("cp.async.wait_group %0;" :: "n"(n) : "memory")

__device__ __forceinline__ void bsplit(float x, __nv_bfloat16& h, __nv_bfloat16& l) {
    h = __float2bfloat16(x);
    l = __float2bfloat16(x - __bfloat162float(h));
}

// ---------------- init / router / scan / aux --------------------------------
__global__ void init_kernel() {
    int i = threadIdx.x;
    if (i < NEXP) { g_mcnt[i] = 0; g_psum[i] = 0.f; }
}

__global__ void router_kernel(const float* __restrict__ x,
                              const float* __restrict__ rw) {
    __shared__ float s_rw[DMODEL * NEXP];
    __shared__ float s_psum[NEXP];
    int tid = threadIdx.x;
    if (tid < NEXP) s_psum[tid] = 0.f;
    for (int i = tid; i < DMODEL * NEXP / 4; i += blockDim.x)
        ((float4*)s_rw)[i] = ((const float4*)rw)[i];
    __syncthreads();

    int warp = tid >> 5, lane = tid & 31;
    int t = blockIdx.x * 8 + warp;

    float acc[NEXP];
#pragma unroll
    for (int e = 0; e < NEXP; e++) acc[e] = 0.f;
    const float* xr = x + (size_t)t * DMODEL;
    for (int k = lane; k < DMODEL; k += 32) {
        float xv = xr[k];
        float4 r0 = *(const float4*)&s_rw[k * 8];
        float4 r1 = *(const float4*)&s_rw[k * 8 + 4];
        acc[0] = fmaf(xv, r0.x, acc[0]); acc[1] = fmaf(xv, r0.y, acc[1]);
        acc[2] = fmaf(xv, r0.z, acc[2]); acc[3] = fmaf(xv, r0.w, acc[3]);
        acc[4] = fmaf(xv, r1.x, acc[4]); acc[5] = fmaf(xv, r1.y, acc[5]);
        acc[6] = fmaf(xv, r1.z, acc[6]); acc[7] = fmaf(xv, r1.w, acc[7]);
    }
#pragma unroll
    for (int e = 0; e < NEXP; e++) {
#pragma unroll
        for (int o = 16; o > 0; o >>= 1)
            acc[e] += __shfl_xor_sync(0xffffffffu, acc[e], o);
    }

    if (lane == 0) {
        float mx = acc[0];
#pragma unroll
        for (int e = 1; e < NEXP; e++) mx = fmaxf(mx, acc[e]);
        float p[NEXP]; float s = 0.f;
#pragma unroll
        for (int e = 0; e < NEXP; e++) { p[e] = expf(acc[e] - mx); s += p[e]; }
        float inv = 1.f / s;
#pragma unroll
        for (int e = 0; e < NEXP; e++) p[e] *= inv;
#pragma unroll
        for (int e = 0; e < NEXP; e++) atomicAdd(&s_psum[e], p[e]);

        float tmp[NEXP];
#pragma unroll
        for (int e = 0; e < NEXP; e++) tmp[e] = p[e];
        float sp[KMAX]; int si[KMAX];
        for (int j = 0; j < KMAX; j++) {
            float best = tmp[0]; int bi = 0;
            for (int e = 1; e < NEXP; e++)
                if (tmp[e] > best) { best = tmp[e]; bi = e; }
            sp[j] = best; si[j] = bi; tmp[bi] = -1.f;
        }
        float csum = 0.f, wsum = 0.f; bool keep[KMAX];
        for (int j = 0; j < KMAX; j++) {
            keep[j] = (j < 1) || (csum < TOPP);
            csum += sp[j];
            if (keep[j]) wsum += sp[j];
        }
        wsum = fmaxf(wsum, 1e-9f);
        for (int j = 0; j < KMAX; j++) g_sel_e[t * KMAX + j] = -1;
        for (int j = 0; j < KMAX; j++)
            if (keep[j]) {
                int pos = atomicAdd(&g_mcnt[si[j]], 1);
                g_idx[si[j] * NTOK + pos] = t;
                g_sel_e[t * KMAX + j]   = si[j];
                g_sel_pos[t * KMAX + j] = pos;
                g_sel_w[t * KMAX + j]   = sp[j] / wsum;
            }
    }
    __syncthreads();
    if (tid < NEXP) atomicAdd(&g_psum[tid], s_psum[tid]);
}

__global__ void scan_kernel() {
    if (threadIdx.x == 0) {
        int o = 0;
        for (int e = 0; e < NEXP; e++) { g_off[e] = o; o += g_mcnt[e]; }
    }
}

__global__ void aux_kernel(float* __restrict__ out_aux) {
    if (threadIdx.x == 0) {
        float tot = 0.f;
        for (int e = 0; e < NEXP; e++) tot += (float)g_mcnt[e];
        tot = fmaxf(tot, 1.f);
        float a = 0.f;
        for (int e = 0; e < NEXP; e++)
            a += ((float)g_mcnt[e] / tot) * (g_psum[e] / (float)NTOK);
        *out_aux = 0.01f * (float)NEXP * a;
    }
}

// ---------------- bf16 split pre-passes --------------------------------------
__global__ void convx_kernel(const float* __restrict__ x) {
    int i = blockIdx.x * blockDim.x + threadIdx.x;   // float4 index
    float4 v = ((const float4*)x)[i];
    __nv_bfloat16 h0, l0, h1, l1, h2, l2, h3, l3;
    bsplit(v.x, h0, l0); bsplit(v.y, h1, l1);
    bsplit(v.z, h2, l2); bsplit(v.w, h3, l3);
    __nv_bfloat162* ph = (__nv_bfloat162*)g_Xh;
    __nv_bfloat162* pl = (__nv_bfloat162*)g_Xl;
    ph[i * 2]     = __nv_bfloat162{h0, h1};
    ph[i * 2 + 1] = __nv_bfloat162{h2, h3};
    pl[i * 2]     = __nv_bfloat162{l0, l1};
    pl[i * 2 + 1] = __nv_bfloat162{l2, l3};
}

// in[z][R][C] fp32 -> out[z][C][R] bf16 hi/lo.  which: 0 -> W1t, 1 -> W2t
__global__ void transpose_split_kernel(const float* __restrict__ in, int which,
                                       int R, int C) {
    __shared__ float tile[32][33];
    __nv_bfloat16* outH = which ? g_W2tH : g_W1tH;
    __nv_bfloat16* outL = which ? g_W2tL : g_W1tL;
    int z = blockIdx.z;
    const float* src = in + (size_t)z * R * C;
    int c0 = blockIdx.x * 32, r0 = blockIdx.y * 32;
    int tx = threadIdx.x, ty = threadIdx.y;
#pragma unroll
    for (int j = 0; j < 32; j += 8)
        tile[ty + j][tx] = src[(size_t)(r0 + ty + j) * C + c0 + tx];
    __syncthreads();
    size_t ob = (size_t)z * R * C;
#pragma unroll
    for (int j = 0; j < 32; j += 8) {
        float v = tile[tx][ty + j];
        __nv_bfloat16 h, l;
        bsplit(v, h, l);
        size_t o = ob + (size_t)(c0 + ty + j) * R + r0 + tx;
        outH[o] = h;
        outL[o] = l;
    }
}

// ---------------- bf16x3 MMA compute for one 128x128x32 k-tile ---------------
// ldmatrix-based fragment loads. aoff0/boff0 are per-lane offsets within a stage.
__device__ __forceinline__ void compute_ktile(uint32_t sb, float acc[2][8][4],
                                              uint32_t aoff0, uint32_t boff0) {
#pragma unroll
    for (int ks = 0; ks < 2; ks++) {
        uint32_t ah[2][4], al[2][4];
#pragma unroll
        for (int mt = 0; mt < 2; mt++) {
            uint32_t aa = sb + aoff0 + mt * (16 * APAD_B) + ks * 32;
            ldsm4(ah[mt], aa);
            ldsm4(al[mt], aa + TERM_B);
        }
#pragma unroll
        for (int j = 0; j < 4; j++) {
            uint32_t ba = sb + 2 * TERM_B + boff0 + j * (16 * APAD_B) + ks * 32;
            uint32_t bh[4], bl[4];
            ldsm4(bh, ba);
            ldsm4(bl, ba + TERM_B);
#pragma unroll
            for (int mt = 0; mt < 2; mt++) {
                mma16816(acc[mt][2 * j],     ah[mt], bh[0], bh[1]);
                mma16816(acc[mt][2 * j],     ah[mt], bl[0], bl[1]);
                mma16816(acc[mt][2 * j],     al[mt], bh[0], bh[1]);
                mma16816(acc[mt][2 * j + 1], ah[mt], bh[2], bh[3]);
                mma16816(acc[mt][2 * j + 1], ah[mt], bl[2], bl[3]);
                mma16816(acc[mt][2 * j + 1], al[mt], bh[2], bh[3]);
            }
        }
    }
}

// cp.async fill of one stage: 8 x 16B per thread (Ah, Al, Bh, Bl x 2 slots)
__device__ __forceinline__ void issue_stage(uint32_t sb,
        const char* pA0h, const char* pA0l, const char* pB0h, const char* pB0l,
        const char* pA1h, const char* pA1l, const char* pB1h, const char* pB1l,
        uint32_t so0, uint32_t so1, int kB) {
    cpasync16(sb + so0,              pA0h + kB);
    cpasync16(sb + TERM_B + so0,     pA0l + kB);
    cpasync16(sb + 2 * TERM_B + so0, pB0h + kB);
    cpasync16(sb + 3 * TERM_B + so0, pB0l + kB);
    cpasync16(sb + so1,              pA1h + kB);
    cpasync16(sb + TERM_B + so1,     pA1l + kB);
    cpasync16(sb + 2 * TERM_B + so1, pB1h + kB);
    cpasync16(sb + 3 * TERM_B + so1, pB1l + kB);
}

// GEMM1: H(hi/lo bf16) = gelu(X[idx] @ W1_e + b1_e), all experts batched
__global__ void __launch_bounds__(256, 2) gemm1_mma(const float* __restrict__ b1) {
    int e = blockIdx.z;
    int m_e = g_mcnt[e];
    int m0 = blockIdx.y * BM;
    if (m0 >= m_e) return;
    int n0 = blockIdx.x * BN;

    extern __shared__ char smem[];
    __shared__ int s_idx[BM];

    int tid = threadIdx.x;
    if (tid < BM) {
        int r = m0 + tid;
        s_idx[tid] = g_idx[e * NTOK + (r < m_e ? r : m_e - 1)];
    }
    __syncthreads();

    uint32_t sbase = smem_u32(smem);

    // copy-lane assignment: 2 slots, slot -> (row, 16B-group)
    int r0s = (tid * 2) >> 2,     c40 = (tid * 2) & 3;
    int r1s = (tid * 2 + 1) >> 2, c41 = (tid * 2 + 1) & 3;
    const char* pA0h = (const char*)(g_Xh + (size_t)s_idx[r0s] * DMODEL) + c40 * 16;
    const char* pA1h = (const char*)(g_Xh + (size_t)s_idx[r1s] * DMODEL) + c41 * 16;
    const char* pA0l = (const char*)(g_Xl + (size_t)s_idx[r0s] * DMODEL) + c40 * 16;
    const char* pA1l = (const char*)(g_Xl + (size_t)s_idx[r1s] * DMODEL) + c41 * 16;
    const char* pB0h = (const char*)(g_W1tH + ((size_t)e * DFF + n0 + r0s) * DMODEL) + c40 * 16;
    const char* pB1h = (const char*)(g_W1tH + ((size_t)e * DFF + n0 + r1s) * DMODEL) + c41 * 16;
    const char* pB0l = (const char*)(g_W1tL + ((size_t)e * DFF + n0 + r0s) * DMODEL) + c40 * 16;
    const char* pB1l = (const char*)(g_W1tL + ((size_t)e * DFF + n0 + r1s) * DMODEL) + c41 * 16;
    uint32_t so0 = r0s * APAD_B + c40 * 16;
    uint32_t so1 = r1s * APAD_B + c41 * 16;

    int wid = tid >> 5, lane = tid & 31;
    int warp_m = wid & 3, warp_n = wid >> 2;
    int qid = lane >> 2, qp = lane & 3;
    uint32_t aoff0 = (warp_m * 32 + (lane & 15)) * APAD_B + (lane >> 4) * 16;
    uint32_t boff0 = (warp_n * 64 + ((lane >> 4) & 1) * 8 + (lane & 7)) * APAD_B
                     + ((lane >> 3) & 1) * 16;

    float acc[2][8][4];
#pragma unroll
    for (int mt = 0; mt < 2; mt++)
#pragma unroll
        for (int nt = 0; nt < 8; nt++)
#pragma unroll
            for (int q = 0; q < 4; q++) acc[mt][nt][q] = 0.f;

    issue_stage(sbase, pA0h, pA0l, pB0h, pB0l, pA1h, pA1l, pB1h, pB1l, so0, so1, 0);
    CP_COMMIT();

    const int T = DMODEL / BKT;   // 16
    for (int t = 0; t < T; t++) {
        if (t + 1 < T) {
            issue_stage(sbase + ((t + 1) & 1) * STAGE_B,
                        pA0h, pA0l, pB0h, pB0l, pA1h, pA1l, pB1h, pB1l,
                        so0, so1, (t + 1) * 64);
            CP_COMMIT();
            CP_WAIT(1);
        } else {
            CP_WAIT(0);
        }
        __syncthreads();
        compute_ktile(sbase + (t & 1) * STAGE_B, acc, aoff0, boff0);
        __syncthreads();
    }

    // epilogue: gelu + bf16 split -> g_HH / g_HL
    int off = g_off[e];
    float2 bv[8];
    const float* b1p = b1 + e * DFF + n0 + warp_n * 64 + qp * 2;
#pragma unroll
    for (int nt = 0; nt < 8; nt++)
        bv[nt] = *(const float2*)(b1p + nt * 8);

#pragma unroll
    for (int mt = 0; mt < 2; mt++) {
#pragma unroll
        for (int half = 0; half < 2; half++) {
            int rl = warp_m * 32 + mt * 16 + half * 8 + qid;
            if (m0 + rl < m_e) {
                size_t rb = (size_t)(off + m0 + rl) * DFF;
#pragma unroll
                for (int nt = 0; nt < 8; nt++) {
                    int col = n0 + warp_n * 64 + nt * 8 + qp * 2;
                    float v0 = acc[mt][nt][half * 2 + 0] + bv[nt].x;
                    float v1 = acc[mt][nt][half * 2 + 1] + bv[nt].y;
                    float gg0 = 0.5f * v0 * (1.0f + erff(v0 * 0.7071067811865475f));
                    float gg1 = 0.5f * v1 * (1.0f + erff(v1 * 0.7071067811865475f));
                    __nv_bfloat16 h0, l0, h1, l1;
                    bsplit(gg0, h0, l0);
                    bsplit(gg1, h1, l1);
                    *(__nv_bfloat162*)(g_HH + rb + col) = __nv_bfloat162{h0, h1};
                    *(__nv_bfloat162*)(g_HL + rb + col) = __nv_bfloat162{l0, l1};
                }
            }
        }
    }
}

// GEMM2: g_P = H @ W2_e + b2_e (per-expert partial rows, all experts batched)
__global__ void __launch_bounds__(256, 2) gemm2_mma(const float* __restrict__ b2) {
    int e = blockIdx.z;
    int m_e = g_mcnt[e];
    int m0 = blockIdx.y * BM;
    if (m0 >= m_e) return;
    int n0 = blockIdx.x * BN;
    int off = g_off[e];

    extern __shared__ char smem[];
    int tid = threadIdx.x;
    uint32_t sbase = smem_u32(smem);

    int r0s = (tid * 2) >> 2,     c40 = (tid * 2) & 3;
    int r1s = (tid * 2 + 1) >> 2, c41 = (tid * 2 + 1) & 3;
    int rr0 = m0 + r0s; if (rr0 >= m_e) rr0 = m_e - 1;
    int rr1 = m0 + r1s; if (rr1 >= m_e) rr1 = m_e - 1;
    const char* pA0h = (const char*)(g_HH + (size_t)(off + rr0) * DFF) + c40 * 16;
    const char* pA1h = (const char*)(g_HH + (size_t)(off + rr1) * DFF) + c41 * 16;
    const char* pA0l = (const char*)(g_HL + (size_t)(off + rr0) * DFF) + c40 * 16;
    const char* pA1l = (const char*)(g_HL + (size_t)(off + rr1) * DFF) + c41 * 16;
    const char* pB0h = (const char*)(g_W2tH + ((size_t)e * DMODEL + n0 + r0s) * DFF) + c40 * 16;
    const char* pB1h = (const char*)(g_W2tH + ((size_t)e * DMODEL + n0 + r1s) * DFF) + c41 * 16;
    const char* pB0l = (const char*)(g_W2tL + ((size_t)e * DMODEL + n0 + r0s) * DFF) + c40 * 16;
    const char* pB1l = (const char*)(g_W2tL + ((size_t)e * DMODEL + n0 + r1s) * DFF) + c41 * 16;
    uint32_t so0 = r0s * APAD_B + c40 * 16;
    uint32_t so1 = r1s * APAD_B + c41 * 16;

    int wid = tid >> 5, lane = tid & 31;
    int warp_m = wid & 3, warp_n = wid >> 2;
    int qid = lane >> 2, qp = lane & 3;
    uint32_t aoff0 = (warp_m * 32 + (lane & 15)) * APAD_B + (lane >> 4) * 16;
    uint32_t boff0 = (warp_n * 64 + ((lane >> 4) & 1) * 8 + (lane & 7)) * APAD_B
                     + ((lane >> 3) & 1) * 16;

    float acc[2][8][4];
#pragma unroll
    for (int mt = 0; mt < 2; mt++)
#pragma unroll
        for (int nt = 0; nt < 8; nt++)
#pragma unroll
            for (int q = 0; q < 4; q++) acc[mt][nt][q] = 0.f;

    issue_stage(sbase, pA0h, pA0l, pB0h, pB0l, pA1h, pA1l, pB1h, pB1l, so0, so1, 0);
    CP_COMMIT();

    const int T = DFF / BKT;   // 64
    for (int t = 0; t < T; t++) {
        if (t + 1 < T) {
            issue_stage(sbase + ((t + 1) & 1) * STAGE_B,
                        pA0h, pA0l, pB0h, pB0l, pA1h, pA1l, pB1h, pB1l,
                        so0, so1, (t + 1) * 64);
            CP_COMMIT();
            CP_WAIT(1);
        } else {
            CP_WAIT(0);
        }
        __syncthreads();
        compute_ktile(sbase + (t & 1) * STAGE_B, acc, aoff0, boff0);
        __syncthreads();
    }

    // epilogue: + b2 -> fp32 partials g_P
    float2 bv[8];
    const float* b2p = b2 + e * DMODEL + n0 + warp_n * 64 + qp * 2;
#pragma unroll
    for (int nt = 0; nt < 8; nt++)
        bv[nt] = *(const float2*)(b2p + nt * 8);

#pragma unroll
    for (int mt = 0; mt < 2; mt++) {
#pragma unroll
        for (int half = 0; half < 2; half++) {
            int rl = warp_m * 32 + mt * 16 + half * 8 + qid;
            if (m0 + rl < m_e) {
                size_t rb = (size_t)(off + m0 + rl) * DMODEL;
#pragma unroll
                for (int nt = 0; nt < 8; nt++) {
                    int col = n0 + warp_n * 64 + nt * 8 + qp * 2;
                    float2 v;
                    v.x = acc[mt][nt][half * 2 + 0] + bv[nt].x;
                    v.y = acc[mt][nt][half * 2 + 1] + bv[nt].y;
                    *(float2*)(g_P + rb + col) = v;
                }
            }
        }
    }
}

// ---------------- combine: out[tok] = sum_j w_j * P[row_j] -------------------
__global__ void combine_kernel(float* __restrict__ out) {
    int tok = blockIdx.x;
    int c = threadIdx.x * 4;
    float4 acc = make_float4(0.f, 0.f, 0.f, 0.f);
#pragma unroll
    for (int j = 0; j < KMAX; j++) {
        int e = g_sel_e[tok * KMAX + j];
        if (e >= 0) {
            float w = g_sel_w[tok * KMAX + j];
            int row = g_off[e] + g_sel_pos[tok * KMAX + j];
            float4 p = *(const float4*)(g_P + (size_t)row * DMODEL + c);
            acc.x += w * p.x; acc.y += w * p.y;
            acc.z += w * p.z; acc.w += w * p.w;
        }
    }
    *(float4*)(out + (size_t)tok * DMODEL + c) = acc;
}

// ---------------- launch ------------------------------------------------------
extern "C" void kernel_launch(void* const* d_in, const int* in_sizes, int n_in,
                              void* d_out, int out_size) {
    const float* x  = (const float*)d_in[0];
    const float* rw = (const float*)d_in[1];
    const float* W1 = (const float*)d_in[2];
    const float* b1 = (const float*)d_in[3];
    const float* W2 = (const float*)d_in[4];
    const float* b2 = (const float*)d_in[5];
    float* out = (float*)d_out;

    cudaFuncSetAttribute(gemm1_mma, cudaFuncAttributeMaxDynamicSharedMemorySize, DYN_SMEM);
    cudaFuncSetAttribute(gemm2_mma, cudaFuncAttributeMaxDynamicSharedMemorySize, DYN_SMEM);

    init_kernel<<<1, 32>>>();
    router_kernel<<<NTOK / 8, 256>>>(x, rw);
    scan_kernel<<<1, 32>>>();

    convx_kernel<<<NTOK * DMODEL / 4 / 256, 256>>>(x);
    transpose_split_kernel<<<dim3(DFF / 32, DMODEL / 32, NEXP), dim3(32, 8)>>>(
        W1, 0, DMODEL, DFF);
    transpose_split_kernel<<<dim3(DMODEL / 32, DFF / 32, NEXP), dim3(32, 8)>>>(
        W2, 1, DFF, DMODEL);

    gemm1_mma<<<dim3(DFF / BN, NTOK / BM, NEXP), 256, DYN_SMEM>>>(b1);
    gemm2_mma<<<dim3(DMODEL / BN, NTOK / BM, NEXP), 256, DYN_SMEM>>>(b2);

    combine_kernel<<<NTOK, 128>>>(out);

    if (out_size > NTOK * DMODEL)
        aux_kernel<<<1, 32>>>(out + (size_t)NTOK * DMODEL);
}

// round 17
// speedup vs baseline: 5.4311x; 1.0775x over previous
#include <cuda_runtime.h>
#include <cuda_bf16.h>
#include <math.h>
#include <stdint.h>

#define NTOK   8192
#define DMODEL 512
#define DFF    2048
#define NEXP   8
#define KMAX   4
#define TOPP   0.9f
#define MAXROWS (KMAX * NTOK)

#define BM 128
#define BN 128
#define BKT 32            // k per smem stage (bf16 elems)
#define APAD_B 80         // padded bytes per 32-elem bf16 row (64 data + 16 pad)
#define TERM_B (128 * APAD_B)      // 10240 bytes per term tile
#define STAGE_B (4 * TERM_B)       // Ah, Al, Bh, Bl
#define DYN_SMEM (2 * STAGE_B)     // 81920

// ---------------- device scratch (static; no allocations) -------------------
__device__ __align__(16) __nv_bfloat16 g_Xh[NTOK * DMODEL];
__device__ __align__(16) __nv_bfloat16 g_Xl[NTOK * DMODEL];
__device__ __align__(16) __nv_bfloat16 g_W1tH[NEXP * DFF * DMODEL];  // [e][n][k]
__device__ __align__(16) __nv_bfloat16 g_W1tL[NEXP * DFF * DMODEL];
__device__ __align__(16) __nv_bfloat16 g_W2tH[NEXP * DMODEL * DFF];  // [e][n][k]
__device__ __align__(16) __nv_bfloat16 g_W2tL[NEXP * DMODEL * DFF];
__device__ __align__(16) __nv_bfloat16 g_HH[(size_t)MAXROWS * DFF];
__device__ __align__(16) __nv_bfloat16 g_HL[(size_t)MAXROWS * DFF];
__device__ __align__(16) float g_P[(size_t)MAXROWS * DMODEL];
__device__ int   g_idx[NEXP * NTOK];
__device__ int   g_sel_e[NTOK * KMAX];
__device__ int   g_sel_pos[NTOK * KMAX];
__device__ float g_sel_w[NTOK * KMAX];
__device__ int   g_mcnt[NEXP];
__device__ int   g_off[NEXP];
__device__ float g_psum[NEXP];

// ---------------- helpers -----------------------------------------------------
__device__ __forceinline__ uint32_t smem_u32(const void* p) {
    uint32_t a;
    asm("{ .reg .u64 t; cvta.to.shared.u64 t, %1; cvt.u32.u64 %0, t; }"
        : "=r"(a) : "l"(p));
    return a;
}
__device__ __forceinline__ void mma16816(float* c, const uint32_t a[4],
                                         uint32_t b0, uint32_t b1) {
    asm volatile(
        "mma.sync.aligned.m16n8k16.row.col.f32.bf16.bf16.f32 "
        "{%0,%1,%2,%3}, {%4,%5,%6,%7}, {%8,%9}, {%0,%1,%2,%3};"
        : "+f"(c[0]), "+f"(c[1]), "+f"(c[2]), "+f"(c[3])
        : "r"(a[0]), "r"(a[1]), "r"(a[2]), "r"(a[3]), "r"(b0), "r"(b1));
}
__device__ __forceinline__ void ldsm4(uint32_t* r, uint32_t addr) {
    asm volatile("ldmatrix.sync.aligned.m8n8.x4.shared.b16 {%0,%1,%2,%3}, [%4];"
        : "=r"(r[0]), "=r"(r[1]), "=r"(r[2]), "=r"(r[3]) : "r"(addr));
}
__device__ __forceinline__ void cpasync16(uint32_t dst, const void* src) {
    asm volatile("cp.async.cg.shared.global [%0], [%1], 16;"
        :: "r"(dst), "l"(src) : "memory");
}
#define CP_COMMIT() asm volatile("cp.async.commit_group;" ::: "memory")
#define CP_WAIT(n)  asm volatile("cp.async.wait_group %0;" :: "n"(n) : "memory")

__device__ __forceinline__ void bsplit(float x, __nv_bfloat16& h, __nv_bfloat16& l) {
    h = __float2bfloat16(x);
    l = __float2bfloat16(x - __bfloat162float(h));
}

// ---------------- init / router / scan / aux --------------------------------
__global__ void init_kernel() {
    int i = threadIdx.x;
    if (i < NEXP) { g_mcnt[i] = 0; g_psum[i] = 0.f; }
}

__global__ void router_kernel(const float* __restrict__ x,
                              const float* __restrict__ rw) {
    __shared__ float s_rw[DMODEL * NEXP];
    __shared__ float s_psum[NEXP];
    int tid = threadIdx.x;
    if (tid < NEXP) s_psum[tid] = 0.f;
    for (int i = tid; i < DMODEL * NEXP / 4; i += blockDim.x)
        ((float4*)s_rw)[i] = ((const float4*)rw)[i];
    __syncthreads();

    int warp = tid >> 5, lane = tid & 31;
    int t = blockIdx.x * 8 + warp;

    float acc[NEXP];
#pragma unroll
    for (int e = 0; e < NEXP; e++) acc[e] = 0.f;
    const float* xr = x + (size_t)t * DMODEL;
    for (int k = lane; k < DMODEL; k += 32) {
        float xv = xr[k];
        float4 r0 = *(const float4*)&s_rw[k * 8];
        float4 r1 = *(const float4*)&s_rw[k * 8 + 4];
        acc[0] = fmaf(xv, r0.x, acc[0]); acc[1] = fmaf(xv, r0.y, acc[1]);
        acc[2] = fmaf(xv, r0.z, acc[2]); acc[3] = fmaf(xv, r0.w, acc[3]);
        acc[4] = fmaf(xv, r1.x, acc[4]); acc[5] = fmaf(xv, r1.y, acc[5]);
        acc[6] = fmaf(xv, r1.z, acc[6]); acc[7] = fmaf(xv, r1.w, acc[7]);
    }
#pragma unroll
    for (int e = 0; e < NEXP; e++) {
#pragma unroll
        for (int o = 16; o > 0; o >>= 1)
            acc[e] += __shfl_xor_sync(0xffffffffu, acc[e], o);
    }

    if (lane == 0) {
        float mx = acc[0];
#pragma unroll
        for (int e = 1; e < NEXP; e++) mx = fmaxf(mx, acc[e]);
        float p[NEXP]; float s = 0.f;
#pragma unroll
        for (int e = 0; e < NEXP; e++) { p[e] = expf(acc[e] - mx); s += p[e]; }
        float inv = 1.f / s;
#pragma unroll
        for (int e = 0; e < NEXP; e++) p[e] *= inv;
#pragma unroll
        for (int e = 0; e < NEXP; e++) atomicAdd(&s_psum[e], p[e]);

        float tmp[NEXP];
#pragma unroll
        for (int e = 0; e < NEXP; e++) tmp[e] = p[e];
        float sp[KMAX]; int si[KMAX];
        for (int j = 0; j < KMAX; j++) {
            float best = tmp[0]; int bi = 0;
            for (int e = 1; e < NEXP; e++)
                if (tmp[e] > best) { best = tmp[e]; bi = e; }
            sp[j] = best; si[j] = bi; tmp[bi] = -1.f;
        }
        float csum = 0.f, wsum = 0.f; bool keep[KMAX];
        for (int j = 0; j < KMAX; j++) {
            keep[j] = (j < 1) || (csum < TOPP);
            csum += sp[j];
            if (keep[j]) wsum += sp[j];
        }
        wsum = fmaxf(wsum, 1e-9f);
        for (int j = 0; j < KMAX; j++) g_sel_e[t * KMAX + j] = -1;
        for (int j = 0; j < KMAX; j++)
            if (keep[j]) {
                int pos = atomicAdd(&g_mcnt[si[j]], 1);
                g_idx[si[j] * NTOK + pos] = t;
                g_sel_e[t * KMAX + j]   = si[j];
                g_sel_pos[t * KMAX + j] = pos;
                g_sel_w[t * KMAX + j]   = sp[j] / wsum;
            }
    }
    __syncthreads();
    if (tid < NEXP) atomicAdd(&g_psum[tid], s_psum[tid]);
}

__global__ void scan_kernel() {
    if (threadIdx.x == 0) {
        int o = 0;
        for (int e = 0; e < NEXP; e++) { g_off[e] = o; o += g_mcnt[e]; }
    }
}

__global__ void aux_kernel(float* __restrict__ out_aux) {
    if (threadIdx.x == 0) {
        float tot = 0.f;
        for (int e = 0; e < NEXP; e++) tot += (float)g_mcnt[e];
        tot = fmaxf(tot, 1.f);
        float a = 0.f;
        for (int e = 0; e < NEXP; e++)
            a += ((float)g_mcnt[e] / tot) * (g_psum[e] / (float)NTOK);
        *out_aux = 0.01f * (float)NEXP * a;
    }
}

// ---------------- bf16 split pre-passes --------------------------------------
__global__ void convx_kernel(const float* __restrict__ x) {
    int i = blockIdx.x * blockDim.x + threadIdx.x;   // float4 index
    float4 v = ((const float4*)x)[i];
    __nv_bfloat16 h0, l0, h1, l1, h2, l2, h3, l3;
    bsplit(v.x, h0, l0); bsplit(v.y, h1, l1);
    bsplit(v.z, h2, l2); bsplit(v.w, h3, l3);
    __nv_bfloat162* ph = (__nv_bfloat162*)g_Xh;
    __nv_bfloat162* pl = (__nv_bfloat162*)g_Xl;
    ph[i * 2]     = __nv_bfloat162{h0, h1};
    ph[i * 2 + 1] = __nv_bfloat162{h2, h3};
    pl[i * 2]     = __nv_bfloat162{l0, l1};
    pl[i * 2 + 1] = __nv_bfloat162{l2, l3};
}

// in[z][R][C] fp32 -> out[z][C][R] bf16 hi/lo.  which: 0 -> W1t, 1 -> W2t
__global__ void transpose_split_kernel(const float* __restrict__ in, int which,
                                       int R, int C) {
    __shared__ float tile[32][33];
    __nv_bfloat16* outH = which ? g_W2tH : g_W1tH;
    __nv_bfloat16* outL = which ? g_W2tL : g_W1tL;
    int z = blockIdx.z;
    const float* src = in + (size_t)z * R * C;
    int c0 = blockIdx.x * 32, r0 = blockIdx.y * 32;
    int tx = threadIdx.x, ty = threadIdx.y;
#pragma unroll
    for (int j = 0; j < 32; j += 8)
        tile[ty + j][tx] = src[(size_t)(r0 + ty + j) * C + c0 + tx];
    __syncthreads();
    size_t ob = (size_t)z * R * C;
#pragma unroll
    for (int j = 0; j < 32; j += 8) {
        float v = tile[tx][ty + j];
        __nv_bfloat16 h, l;
        bsplit(v, h, l);
        size_t o = ob + (size_t)(c0 + ty + j) * R + r0 + tx;
        outH[o] = h;
        outL[o] = l;
    }
}

// ---------------- bf16x3 MMA compute for one 128x128x32 k-tile ---------------
// ldmatrix-based fragment loads. aoff0/boff0 are per-lane offsets within a stage.
__device__ __forceinline__ void compute_ktile(uint32_t sb, float acc[2][8][4],
                                              uint32_t aoff0, uint32_t boff0) {
#pragma unroll
    for (int ks = 0; ks < 2; ks++) {
        uint32_t ah[2][4], al[2][4];
#pragma unroll
        for (int mt = 0; mt < 2; mt++) {
            uint32_t aa = sb + aoff0 + mt * (16 * APAD_B) + ks * 32;
            ldsm4(ah[mt], aa);
            ldsm4(al[mt], aa + TERM_B);
        }
#pragma unroll
        for (int j = 0; j < 4; j++) {
            uint32_t ba = sb + 2 * TERM_B + boff0 + j * (16 * APAD_B) + ks * 32;
            uint32_t bh[4], bl[4];
            ldsm4(bh, ba);
            ldsm4(bl, ba + TERM_B);
#pragma unroll
            for (int mt = 0; mt < 2; mt++) {
                mma16816(acc[mt][2 * j],     ah[mt], bh[0], bh[1]);
                mma16816(acc[mt][2 * j],     ah[mt], bl[0], bl[1]);
                mma16816(acc[mt][2 * j],     al[mt], bh[0], bh[1]);
                mma16816(acc[mt][2 * j + 1], ah[mt], bh[2], bh[3]);
                mma16816(acc[mt][2 * j + 1], ah[mt], bl[2], bl[3]);
                mma16816(acc[mt][2 * j + 1], al[mt], bh[2], bh[3]);
            }
        }
    }
}

// cp.async fill of one stage: 8 x 16B per thread (Ah, Al, Bh, Bl x 2 slots)
__device__ __forceinline__ void issue_stage(uint32_t sb,
        const char* pA0h, const char* pA0l, const char* pB0h, const char* pB0l,
        const char* pA1h, const char* pA1l, const char* pB1h, const char* pB1l,
        uint32_t so0, uint32_t so1, int kB) {
    cpasync16(sb + so0,              pA0h + kB);
    cpasync16(sb + TERM_B + so0,     pA0l + kB);
    cpasync16(sb + 2 * TERM_B + so0, pB0h + kB);
    cpasync16(sb + 3 * TERM_B + so0, pB0l + kB);
    cpasync16(sb + so1,              pA1h + kB);
    cpasync16(sb + TERM_B + so1,     pA1l + kB);
    cpasync16(sb + 2 * TERM_B + so1, pB1h + kB);
    cpasync16(sb + 3 * TERM_B + so1, pB1l + kB);
}

// Single-barrier two-stage mainloop:
//   iter t: wait own cp-groups (buf t ready), sync (also proves every warp
//   finished compute(t-1), freeing buf (t+1)&1), issue cp for t+1, compute t.
#define MAINLOOP(T_) do {                                                       \
    issue_stage(sbase, pA0h, pA0l, pB0h, pB0l, pA1h, pA1l, pB1h, pB1l,          \
                so0, so1, 0);                                                   \
    CP_COMMIT();                                                                \
    for (int t = 0; t < (T_); t++) {                                            \
        CP_WAIT(0);                                                             \
        __syncthreads();                                                        \
        if (t + 1 < (T_)) {                                                     \
            issue_stage(sbase + ((t + 1) & 1) * STAGE_B,                        \
                        pA0h, pA0l, pB0h, pB0l, pA1h, pA1l, pB1h, pB1l,         \
                        so0, so1, (t + 1) * 64);                                \
            CP_COMMIT();                                                        \
        }                                                                       \
        compute_ktile(sbase + (t & 1) * STAGE_B, acc, aoff0, boff0);            \
    }                                                                           \
} while (0)

// GEMM1: H(hi/lo bf16) = gelu(X[idx] @ W1_e + b1_e), all experts batched
__global__ void __launch_bounds__(256, 2) gemm1_mma(const float* __restrict__ b1) {
    int e = blockIdx.z;
    int m_e = g_mcnt[e];
    int m0 = blockIdx.y * BM;
    if (m0 >= m_e) return;
    int n0 = blockIdx.x * BN;

    extern __shared__ char smem[];
    __shared__ int s_idx[BM];

    int tid = threadIdx.x;
    if (tid < BM) {
        int r = m0 + tid;
        s_idx[tid] = g_idx[e * NTOK + (r < m_e ? r : m_e - 1)];
    }
    __syncthreads();

    uint32_t sbase = smem_u32(smem);

    // copy-lane assignment: 2 slots, slot -> (row, 16B-group)
    int r0s = (tid * 2) >> 2,     c40 = (tid * 2) & 3;
    int r1s = (tid * 2 + 1) >> 2, c41 = (tid * 2 + 1) & 3;
    const char* pA0h = (const char*)(g_Xh + (size_t)s_idx[r0s] * DMODEL) + c40 * 16;
    const char* pA1h = (const char*)(g_Xh + (size_t)s_idx[r1s] * DMODEL) + c41 * 16;
    const char* pA0l = (const char*)(g_Xl + (size_t)s_idx[r0s] * DMODEL) + c40 * 16;
    const char* pA1l = (const char*)(g_Xl + (size_t)s_idx[r1s] * DMODEL) + c41 * 16;
    const char* pB0h = (const char*)(g_W1tH + ((size_t)e * DFF + n0 + r0s) * DMODEL) + c40 * 16;
    const char* pB1h = (const char*)(g_W1tH + ((size_t)e * DFF + n0 + r1s) * DMODEL) + c41 * 16;
    const char* pB0l = (const char*)(g_W1tL + ((size_t)e * DFF + n0 + r0s) * DMODEL) + c40 * 16;
    const char* pB1l = (const char*)(g_W1tL + ((size_t)e * DFF + n0 + r1s) * DMODEL) + c41 * 16;
    uint32_t so0 = r0s * APAD_B + c40 * 16;
    uint32_t so1 = r1s * APAD_B + c41 * 16;

    int wid = tid >> 5, lane = tid & 31;
    int warp_m = wid & 3, warp_n = wid >> 2;
    int qid = lane >> 2, qp = lane & 3;
    uint32_t aoff0 = (warp_m * 32 + (lane & 15)) * APAD_B + (lane >> 4) * 16;
    uint32_t boff0 = (warp_n * 64 + ((lane >> 4) & 1) * 8 + (lane & 7)) * APAD_B
                     + ((lane >> 3) & 1) * 16;

    float acc[2][8][4];
#pragma unroll
    for (int mt = 0; mt < 2; mt++)
#pragma unroll
        for (int nt = 0; nt < 8; nt++)
#pragma unroll
            for (int q = 0; q < 4; q++) acc[mt][nt][q] = 0.f;

    MAINLOOP(DMODEL / BKT);   // 16 k-tiles

    // epilogue: gelu + bf16 split -> g_HH / g_HL
    int off = g_off[e];
    float2 bv[8];
    const float* b1p = b1 + e * DFF + n0 + warp_n * 64 + qp * 2;
#pragma unroll
    for (int nt = 0; nt < 8; nt++)
        bv[nt] = *(const float2*)(b1p + nt * 8);

#pragma unroll
    for (int mt = 0; mt < 2; mt++) {
#pragma unroll
        for (int half = 0; half < 2; half++) {
            int rl = warp_m * 32 + mt * 16 + half * 8 + qid;
            if (m0 + rl < m_e) {
                size_t rb = (size_t)(off + m0 + rl) * DFF;
#pragma unroll
                for (int nt = 0; nt < 8; nt++) {
                    int col = n0 + warp_n * 64 + nt * 8 + qp * 2;
                    float v0 = acc[mt][nt][half * 2 + 0] + bv[nt].x;
                    float v1 = acc[mt][nt][half * 2 + 1] + bv[nt].y;
                    float gg0 = 0.5f * v0 * (1.0f + erff(v0 * 0.7071067811865475f));
                    float gg1 = 0.5f * v1 * (1.0f + erff(v1 * 0.7071067811865475f));
                    __nv_bfloat16 h0, l0, h1, l1;
                    bsplit(gg0, h0, l0);
                    bsplit(gg1, h1, l1);
                    *(__nv_bfloat162*)(g_HH + rb + col) = __nv_bfloat162{h0, h1};
                    *(__nv_bfloat162*)(g_HL + rb + col) = __nv_bfloat162{l0, l1};
                }
            }
        }
    }
}

// GEMM2: g_P = H @ W2_e + b2_e (per-expert partial rows, all experts batched)
__global__ void __launch_bounds__(256, 2) gemm2_mma(const float* __restrict__ b2) {
    int e = blockIdx.z;
    int m_e = g_mcnt[e];
    int m0 = blockIdx.y * BM;
    if (m0 >= m_e) return;
    int n0 = blockIdx.x * BN;
    int off = g_off[e];

    extern __shared__ char smem[];
    int tid = threadIdx.x;
    uint32_t sbase = smem_u32(smem);

    int r0s = (tid * 2) >> 2,     c40 = (tid * 2) & 3;
    int r1s = (tid * 2 + 1) >> 2, c41 = (tid * 2 + 1) & 3;
    int rr0 = m0 + r0s; if (rr0 >= m_e) rr0 = m_e - 1;
    int rr1 = m0 + r1s; if (rr1 >= m_e) rr1 = m_e - 1;
    const char* pA0h = (const char*)(g_HH + (size_t)(off + rr0) * DFF) + c40 * 16;
    const char* pA1h = (const char*)(g_HH + (size_t)(off + rr1) * DFF) + c41 * 16;
    const char* pA0l = (const char*)(g_HL + (size_t)(off + rr0) * DFF) + c40 * 16;
    const char* pA1l = (const char*)(g_HL + (size_t)(off + rr1) * DFF) + c41 * 16;
    const char* pB0h = (const char*)(g_W2tH + ((size_t)e * DMODEL + n0 + r0s) * DFF) + c40 * 16;
    const char* pB1h = (const char*)(g_W2tH + ((size_t)e * DMODEL + n0 + r1s) * DFF) + c41 * 16;
    const char* pB0l = (const char*)(g_W2tL + ((size_t)e * DMODEL + n0 + r0s) * DFF) + c40 * 16;
    const char* pB1l = (const char*)(g_W2tL + ((size_t)e * DMODEL + n0 + r1s) * DFF) + c41 * 16;
    uint32_t so0 = r0s * APAD_B + c40 * 16;
    uint32_t so1 = r1s * APAD_B + c41 * 16;

    int wid = tid >> 5, lane = tid & 31;
    int warp_m = wid & 3, warp_n = wid >> 2;
    int qid = lane >> 2, qp = lane & 3;
    uint32_t aoff0 = (warp_m * 32 + (lane & 15)) * APAD_B + (lane >> 4) * 16;
    uint32_t boff0 = (warp_n * 64 + ((lane >> 4) & 1) * 8 + (lane & 7)) * APAD_B
                     + ((lane >> 3) & 1) * 16;

    float acc[2][8][4];
#pragma unroll
    for (int mt = 0; mt < 2; mt++)
#pragma unroll
        for (int nt = 0; nt < 8; nt++)
#pragma unroll
            for (int q = 0; q < 4; q++) acc[mt][nt][q] = 0.f;

    MAINLOOP(DFF / BKT);   // 64 k-tiles

    // epilogue: + b2 -> fp32 partials g_P
    float2 bv[8];
    const float* b2p = b2 + e * DMODEL + n0 + warp_n * 64 + qp * 2;
#pragma unroll
    for (int nt = 0; nt < 8; nt++)
        bv[nt] = *(const float2*)(b2p + nt * 8);

#pragma unroll
    for (int mt = 0; mt < 2; mt++) {
#pragma unroll
        for (int half = 0; half < 2; half++) {
            int rl = warp_m * 32 + mt * 16 + half * 8 + qid;
            if (m0 + rl < m_e) {
                size_t rb = (size_t)(off + m0 + rl) * DMODEL;
#pragma unroll
                for (int nt = 0; nt < 8; nt++) {
                    int col = n0 + warp_n * 64 + nt * 8 + qp * 2;
                    float2 v;
                    v.x = acc[mt][nt][half * 2 + 0] + bv[nt].x;
                    v.y = acc[mt][nt][half * 2 + 1] + bv[nt].y;
                    *(float2*)(g_P + rb + col) = v;
                }
            }
        }
    }
}

// ---------------- combine: out[tok] = sum_j w_j * P[row_j] -------------------
__global__ void combine_kernel(float* __restrict__ out) {
    int tok = blockIdx.x;
    int c = threadIdx.x * 4;
    float4 acc = make_float4(0.f, 0.f, 0.f, 0.f);
#pragma unroll
    for (int j = 0; j < KMAX; j++) {
        int e = g_sel_e[tok * KMAX + j];
        if (e >= 0) {
            float w = g_sel_w[tok * KMAX + j];
            int row = g_off[e] + g_sel_pos[tok * KMAX + j];
            float4 p = *(const float4*)(g_P + (size_t)row * DMODEL + c);
            acc.x += w * p.x; acc.y += w * p.y;
            acc.z += w * p.z; acc.w += w * p.w;
        }
    }
    *(float4*)(out + (size_t)tok * DMODEL + c) = acc;
}

// ---------------- launch ------------------------------------------------------
// Order puts gemm1_mma at launch slot 6 so the ncu capture (-s 5 -c 1) lands
// on the hot GEMM instead of a pre-pass kernel.
extern "C" void kernel_launch(void* const* d_in, const int* in_sizes, int n_in,
                              void* d_out, int out_size) {
    const float* x  = (const float*)d_in[0];
    const float* rw = (const float*)d_in[1];
    const float* W1 = (const float*)d_in[2];
    const float* b1 = (const float*)d_in[3];
    const float* W2 = (const float*)d_in[4];
    const float* b2 = (const float*)d_in[5];
    float* out = (float*)d_out;

    cudaFuncSetAttribute(gemm1_mma, cudaFuncAttributeMaxDynamicSharedMemorySize, DYN_SMEM);
    cudaFuncSetAttribute(gemm2_mma, cudaFuncAttributeMaxDynamicSharedMemorySize, DYN_SMEM);

    init_kernel<<<1, 32>>>();                                            // 1
    router_kernel<<<NTOK / 8, 256>>>(x, rw);                             // 2
    scan_kernel<<<1, 32>>>();                                            // 3
    convx_kernel<<<NTOK * DMODEL / 4 / 256, 256>>>(x);                   // 4
    transpose_split_kernel<<<dim3(DFF / 32, DMODEL / 32, NEXP),          // 5
                             dim3(32, 8)>>>(W1, 0, DMODEL, DFF);
    gemm1_mma<<<dim3(DFF / BN, NTOK / BM, NEXP), 256, DYN_SMEM>>>(b1);   // 6
    transpose_split_kernel<<<dim3(DMODEL / 32, DFF / 32, NEXP),          // 7
                             dim3(32, 8)>>>(W2, 1, DFF, DMODEL);
    gemm2_mma<<<dim3(DMODEL / BN, NTOK / BM, NEXP), 256, DYN_SMEM>>>(b2);// 8
    combine_kernel<<<NTOK, 128>>>(out);                                  // 9

    if (out_size > NTOK * DMODEL)
        aux_kernel<<<1, 32>>>(out + (size_t)NTOK * DMODEL);              // 10
}